// round 12
// baseline (speedup 1.0000x reference)
#include <cuda_runtime.h>
#include <cstdint>

#define NN 10000
#define EE 320000
#define DD 256
#define NDTOT (NN*DD)
#define WSZ 65536

// -------- scratch (static device globals; no allocation) ----------
__device__ float g_q[NDTOT];
__device__ float g_k[NDTOT];
__device__ float g_v[NDTOT];
__device__ float g_s[NDTOT];
__device__ float g_hA[NDTOT];
__device__ float g_hB[NDTOT];
__device__ float g_hrA[NDTOT];    // tf32-rounded h, ping
__device__ float g_hrB[NDTOT];    // tf32-rounded h, pong
__device__ float g_xr[NDTOT];     // tf32-rounded x
__device__ float g_wr[10*WSZ];    // rounded weights: Wq,Wk,Wv,Ws,Wl0..2,Wr0..2
__device__ float g_mean[NDTOT];   // tf32-rounded at production
__device__ float g_z[NDTOT];      // partial h@Wr accumulator
__device__ float g_logits[EE];
__device__ float g_mx[NN];        // per-node logit max
__device__ int   g_rowptr[NN + 1];
__device__ int   g_srcs[EE];
__device__ int   g_cnt[NN];
__device__ int   g_fill[NN];

// -------- helpers ----------
__device__ __forceinline__ float rtf32(float f)
{
    uint32_t u;
    asm("cvt.rna.tf32.f32 %0, %1;" : "=r"(u) : "f"(f));
    return __uint_as_float(u);
}

__device__ __forceinline__ void mma_tf32(float* c, const uint32_t* a, const uint32_t* b)
{
    asm volatile(
        "mma.sync.aligned.m16n8k8.row.col.f32.tf32.tf32.f32 "
        "{%0,%1,%2,%3}, {%4,%5,%6,%7}, {%8,%9}, {%0,%1,%2,%3};"
        : "+f"(c[0]), "+f"(c[1]), "+f"(c[2]), "+f"(c[3])
        : "r"(a[0]), "r"(a[1]), "r"(a[2]), "r"(a[3]), "r"(b[0]), "r"(b[1]));
}

__device__ __forceinline__ void cpasync16(uint32_t dst, const void* src, int szbytes)
{
    asm volatile("cp.async.ca.shared.global [%0], [%1], 16, %2;"
                 :: "r"(dst), "l"(src), "r"(szbytes));
}
__device__ __forceinline__ void cpasync_commit() { asm volatile("cp.async.commit_group;"); }
__device__ __forceinline__ void cpasync_wait1()  { asm volatile("cp.async.wait_group 1;"); }
__device__ __forceinline__ void cpasync_wait0()  { asm volatile("cp.async.wait_group 0;"); }

// -------- prep: tf32-round x and all weights into scratch (float4) --------
__global__ void round_prep(const float4* __restrict__ x,
                           const float4* __restrict__ Wq, const float4* __restrict__ Wk,
                           const float4* __restrict__ Wv, const float4* __restrict__ Ws,
                           const float4* __restrict__ Wl, const float4* __restrict__ Wr)
{
    int i = blockIdx.x * blockDim.x + threadIdx.x;
    const int XV = NDTOT / 4;           // 640000
    const int WV = WSZ / 4;             // 16384
    const int totalv = XV + 10 * WV;
    if (i >= totalv) return;
    float4 v;
    float4* dst;
    if (i < XV) {
        v = x[i];
        dst = reinterpret_cast<float4*>(g_xr) + i;
    } else {
        int j = i - XV;
        int m = j >> 14, o = j & (WV - 1);
        const float4* src;
        if      (m == 0) src = Wq;
        else if (m == 1) src = Wk;
        else if (m == 2) src = Wv;
        else if (m == 3) src = Ws;
        else if (m <  7) src = Wl + (size_t)(m - 4) * WV;
        else             src = Wr + (size_t)(m - 7) * WV;
        v = src[o];
        dst = reinterpret_cast<float4*>(g_wr) + j;
    }
    v.x = rtf32(v.x); v.y = rtf32(v.y); v.z = rtf32(v.z); v.w = rtf32(v.w);
    *dst = v;
}

#define APAD 36
#define BPAD 136
#define ASZ (128*APAD)
#define BSZ (32*BPAD)
#define SMEM_BYTES ((2*ASZ + 2*BSZ) * 4)   // 71680

// ---- issue one chunk (A 128x32 from Asrc at col kt, B 32x128 from Bsrc) ----
#define ISSUE_CHUNK(Asrc, Bsrc, kt, buf)                                        \
    {                                                                           \
        uint32_t abase = sbase + (uint32_t)((buf) * ASZ) * 4u;                  \
        uint32_t bbase = sbase + (uint32_t)(2 * ASZ + (buf) * BSZ) * 4u;        \
        _Pragma("unroll")                                                       \
        for (int i = 0; i < 4; i++) {                                           \
            int idx = i * 256 + tid;                                            \
            int ar = idx >> 3, acq = (idx & 7) * 4;                             \
            int grow = bm + ar;                                                 \
            int sz = (grow < NN) ? 16 : 0;                                      \
            cpasync16(abase + (uint32_t)(ar * APAD + acq) * 4u,                 \
                      (Asrc) + (size_t)grow * DD + (kt) + acq, sz);             \
        }                                                                       \
        _Pragma("unroll")                                                       \
        for (int i = 0; i < 4; i++) {                                           \
            int idx = i * 256 + tid;                                            \
            int br = idx >> 5, bcq = (idx & 31) * 4;                            \
            cpasync16(bbase + (uint32_t)(br * BPAD + bcq) * 4u,                 \
                      (Bsrc) + (size_t)((kt) + br) * DD + bn + bcq, 16);        \
        }                                                                       \
        cpasync_commit();                                                       \
    }

#define COMPUTE_CHUNK(buf)                                                      \
    {                                                                           \
        const float* pA = s_dyn + (buf) * ASZ;                                  \
        const float* pB = s_dyn + 2 * ASZ + (buf) * BSZ;                        \
        _Pragma("unroll")                                                       \
        for (int k8 = 0; k8 < 4; k8++) {                                        \
            const int kb = k8 * 8;                                              \
            uint32_t af[4][4], bf[4][2];                                        \
            _Pragma("unroll")                                                   \
            for (int mt = 0; mt < 4; mt++) {                                    \
                int mr = wm + mt * 16 + fr;                                     \
                af[mt][0] = __float_as_uint(pA[mr * APAD + kb + fc]);           \
                af[mt][1] = __float_as_uint(pA[(mr + 8) * APAD + kb + fc]);     \
                af[mt][2] = __float_as_uint(pA[mr * APAD + kb + fc + 4]);       \
                af[mt][3] = __float_as_uint(pA[(mr + 8) * APAD + kb + fc + 4]); \
            }                                                                   \
            _Pragma("unroll")                                                   \
            for (int nt = 0; nt < 4; nt++) {                                    \
                int nc = wn + nt * 8 + fr;                                      \
                bf[nt][0] = __float_as_uint(pB[(kb + fc) * BPAD + nc]);         \
                bf[nt][1] = __float_as_uint(pB[(kb + fc + 4) * BPAD + nc]);     \
            }                                                                   \
            _Pragma("unroll")                                                   \
            for (int mt = 0; mt < 4; mt++)                                      \
                _Pragma("unroll")                                               \
                for (int nt = 0; nt < 4; nt++)                                  \
                    mma_tf32(acc[mt][nt], af[mt], bf[nt]);                      \
        }                                                                       \
    }

#define GEMM_PROLOGUE()                                                         \
    extern __shared__ float s_dyn[];                                            \
    const uint32_t sbase = (uint32_t)__cvta_generic_to_shared(s_dyn);           \
    const int tid  = threadIdx.x;                                               \
    const int lane = tid & 31;                                                  \
    const int warp = tid >> 5;                                                  \
    const int wm = (warp >> 2) * 64;                                            \
    const int wn = (warp & 3) * 32;                                             \
    const int fr = lane >> 2;                                                   \
    const int fc = lane & 3;                                                    \
    const int bm = blockIdx.x * 128;                                            \
    float acc[4][4][4];                                                         \
    _Pragma("unroll")                                                           \
    for (int mt = 0; mt < 4; mt++)                                              \
        _Pragma("unroll")                                                       \
        for (int nt = 0; nt < 4; nt++)                                          \
            _Pragma("unroll")                                                   \
            for (int r = 0; r < 4; r++) acc[mt][nt][r] = 0.f;

#define GEMM_MAINLOOP(Asrc, Bsrc)                                               \
    {                                                                           \
        const int NC = 8;                                                       \
        ISSUE_CHUNK(Asrc, Bsrc, 0, 0);                                          \
        ISSUE_CHUNK(Asrc, Bsrc, 32, 1);                                         \
        for (int c = 0; c < NC; c++) {                                          \
            if (c + 1 < NC) cpasync_wait1(); else cpasync_wait0();              \
            __syncthreads();                                                    \
            COMPUTE_CHUNK(c & 1);                                               \
            __syncthreads();                                                    \
            if (c + 2 < NC) ISSUE_CHUNK(Asrc, Bsrc, (c + 2) * 32, c & 1);       \
        }                                                                       \
    }

// =====================================================================
// Projection pair: mats (mat0, mat0+1) from g_wr, biases b0/b1.
// grid (79, 4): blockIdx.y>>1 selects which of the two, &1 the N-half.
// =====================================================================
__global__ void __launch_bounds__(256, 2)
gemm_proj(int mat0, const float* __restrict__ b0, const float* __restrict__ b1)
{
    GEMM_PROLOGUE();
    const int midx = blockIdx.y >> 1;
    const int mat  = mat0 + midx;
    const int bn   = (blockIdx.y & 1) * 128;

    const float* B = g_wr + (size_t)mat * WSZ;
    const float* bias = midx ? b1 : b0;
    float* C;
    if      (mat == 0) C = g_q;
    else if (mat == 1) C = g_k;
    else if (mat == 2) C = g_v;
    else               C = g_s;

    GEMM_MAINLOOP(g_xr, B);

    float bb[4][2];
#pragma unroll
    for (int nt = 0; nt < 4; nt++) {
        int col = bn + wn + nt * 8 + fc * 2;
        bb[nt][0] = bias[col]; bb[nt][1] = bias[col + 1];
    }
#pragma unroll
    for (int mt = 0; mt < 4; mt++) {
#pragma unroll
        for (int nt = 0; nt < 4; nt++) {
            int row = bm + wm + mt * 16 + fr;
            int col = bn + wn + nt * 8 + fc * 2;
            if (row < NN) {
                float2 o = make_float2(acc[mt][nt][0] + bb[nt][0], acc[mt][nt][1] + bb[nt][1]);
                *reinterpret_cast<float2*>(&C[(size_t)row * DD + col]) = o;
            }
            if (row + 8 < NN) {
                float2 o = make_float2(acc[mt][nt][2] + bb[nt][0], acc[mt][nt][3] + bb[nt][1]);
                *reinterpret_cast<float2*>(&C[(size_t)(row + 8) * DD + col]) = o;
            }
        }
    }
}

// =====================================================================
// SAGE half 1: g_z = hr_in @ Wr
// =====================================================================
__global__ void __launch_bounds__(256, 2)
gemm_r(const float* __restrict__ Br, const float* __restrict__ hr_in)
{
    GEMM_PROLOGUE();
    const int bn = blockIdx.y * 128;

    GEMM_MAINLOOP(hr_in, Br);

#pragma unroll
    for (int mt = 0; mt < 4; mt++) {
#pragma unroll
        for (int nt = 0; nt < 4; nt++) {
            int row = bm + wm + mt * 16 + fr;
            int col = bn + wn + nt * 8 + fc * 2;
            if (row < NN)
                *reinterpret_cast<float2*>(&g_z[(size_t)row * DD + col]) =
                    make_float2(acc[mt][nt][0], acc[mt][nt][1]);
            if (row + 8 < NN)
                *reinterpret_cast<float2*>(&g_z[(size_t)(row + 8) * DD + col]) =
                    make_float2(acc[mt][nt][2], acc[mt][nt][3]);
        }
    }
}

// =====================================================================
// SAGE half 2: acc = g_mean @ Wl; epilogue adds g_z + bl, BN + gated
// residual (full-precision hin) + relu -> hout (+ rounded hr_out)
// =====================================================================
__global__ void __launch_bounds__(256, 2)
gemm_l(const float* __restrict__ Bl, const float* __restrict__ bl,
       const float* __restrict__ gamma, const float* __restrict__ beta,
       const float* __restrict__ alpha,
       const float* __restrict__ hin,
       float* __restrict__ hout, float* __restrict__ hr_out)
{
    GEMM_PROLOGUE();
    const int bn = blockIdx.y * 128;

    GEMM_MAINLOOP(g_mean, Bl);

    const float al  = 1.f / (1.f + __expf(-alpha[0]));
    const float oma = 1.f - al;
    const float BNS = 0.9999950000374994f;   // 1/sqrt(1+1e-5)

    float blv[4][2], gv[4][2], bev[4][2];
#pragma unroll
    for (int nt = 0; nt < 4; nt++) {
        int col = bn + wn + nt * 8 + fc * 2;
        blv[nt][0] = bl[col];    blv[nt][1] = bl[col + 1];
        gv[nt][0]  = gamma[col]; gv[nt][1]  = gamma[col + 1];
        bev[nt][0] = beta[col];  bev[nt][1] = beta[col + 1];
    }

#pragma unroll
    for (int mt = 0; mt < 4; mt++) {
#pragma unroll
        for (int nt = 0; nt < 4; nt++) {
            int row = bm + wm + mt * 16 + fr;
            int col = bn + wn + nt * 8 + fc * 2;
#pragma unroll
            for (int h = 0; h < 2; h++) {
                int rr = row + h * 8;
                if (rr < NN) {
                    float2 zr = *reinterpret_cast<const float2*>(&g_z[(size_t)rr * DD + col]);
                    float2 rv = *reinterpret_cast<const float2*>(&hin[(size_t)rr * DD + col]);
                    float z0 = fmaf((acc[mt][nt][h*2]   + zr.x + blv[nt][0]) * BNS, gv[nt][0], bev[nt][0]);
                    float z1 = fmaf((acc[mt][nt][h*2+1] + zr.y + blv[nt][1]) * BNS, gv[nt][1], bev[nt][1]);
                    float o0 = fmaxf(fmaf(al, z0, oma * rv.x), 0.f);
                    float o1 = fmaxf(fmaf(al, z1, oma * rv.y), 0.f);
                    *reinterpret_cast<float2*>(&hout[(size_t)rr * DD + col]) = make_float2(o0, o1);
                    if (hr_out) {
                        *reinterpret_cast<float2*>(&hr_out[(size_t)rr * DD + col]) =
                            make_float2(rtf32(o0), rtf32(o1));
                    }
                }
            }
        }
    }
}

// -------- CSR build ----------
__global__ void hist_kernel(const int* __restrict__ ei)
{
    int e = blockIdx.x * blockDim.x + threadIdx.x;
    if (e >= EE) return;
    atomicAdd(&g_cnt[ei[EE + e]], 1);
}

// coalesced smem-staged block scan: 1024 threads x 10 elems
__global__ void scan_kernel()
{
    __shared__ int sh[10240];          // 40 KB
    __shared__ int wsum[32];
    const int tid = threadIdx.x;
    const int lane = tid & 31, wid = tid >> 5;
    const int PER = 10;

    for (int i = tid; i < 10240; i += 1024)
        sh[i] = (i < NN) ? g_cnt[i] : 0;
    __syncthreads();

    int base = tid * PER;
    int loc[PER];
    int s = 0;
#pragma unroll
    for (int j = 0; j < PER; j++) {
        s += sh[base + j];
        loc[j] = s;
    }
    int ssum = s;
#pragma unroll
    for (int off = 1; off < 32; off <<= 1) {
        int t = __shfl_up_sync(0xffffffffu, ssum, off);
        if (lane >= off) ssum += t;
    }
    if (lane == 31) wsum[wid] = ssum;
    __syncthreads();
    if (wid == 0) {
        int w = wsum[lane];
#pragma unroll
        for (int off = 1; off < 32; off <<= 1) {
            int t = __shfl_up_sync(0xffffffffu, w, off);
            if (lane >= off) w += t;
        }
        wsum[lane] = w;
    }
    __syncthreads();

    int offset = ssum - s + (wid > 0 ? wsum[wid - 1] : 0);
#pragma unroll
    for (int j = 0; j < PER; j++)
        sh[base + j] = offset + loc[j];
    __syncthreads();

    if (tid == 0) { g_rowptr[0] = 0; g_fill[0] = 0; }
    for (int i = tid; i < NN; i += 1024) {
        int incl = sh[i];
        g_rowptr[i + 1] = incl;
        if (i > 0) g_fill[i] = sh[i - 1];
    }
}

__global__ void scatter_kernel(const int* __restrict__ ei)
{
    int e = blockIdx.x * blockDim.x + threadIdx.x;
    if (e >= EE) return;
    int src = ei[e];
    int dst = ei[EE + e];
    int pos = atomicAdd(&g_fill[dst], 1);
    g_srcs[pos] = src;
}

// -------- attention pass 1: logits + per-node max (needs q,k,CSR) --------
__global__ void attn_logits()
{
    int gw = (blockIdx.x * blockDim.x + threadIdx.x) >> 5;
    int lane = threadIdx.x & 31;
    if (gw >= NN) return;
    int beg = g_rowptr[gw], end = g_rowptr[gw + 1];

    float qr[8];
#pragma unroll
    for (int r = 0; r < 8; r++) qr[r] = g_q[(size_t)gw * DD + r * 32 + lane];

    float m = -1e30f;
    for (int e = beg; e < end; e++) {
        int src = g_srcs[e];
        const float* kp = &g_k[(size_t)src * DD];
        float p = 0.f;
#pragma unroll
        for (int r = 0; r < 8; r++) p = fmaf(qr[r], kp[r * 32 + lane], p);
#pragma unroll
        for (int off = 16; off; off >>= 1) p += __shfl_xor_sync(0xffffffffu, p, off);
        p *= 0.0625f;
        if (lane == 0) g_logits[e] = p;
        m = fmaxf(m, p);
    }
    if (lane == 0) g_mx[gw] = m;
}

// -------- attention pass 2: softmax-weighted V agg + skip + relu --------
__global__ void attn_agg()
{
    int gw = (blockIdx.x * blockDim.x + threadIdx.x) >> 5;
    int lane = threadIdx.x & 31;
    if (gw >= NN) return;
    int beg = g_rowptr[gw], end = g_rowptr[gw + 1];
    float m = g_mx[gw];

    float acc[8];
#pragma unroll
    for (int r = 0; r < 8; r++) acc[r] = 0.f;
    float ssum = 0.f;
    for (int e = beg; e < end; e++) {
        int src = g_srcs[e];
        float w = __expf(g_logits[e] - m);
        ssum += w;
        const float* vp = &g_v[(size_t)src * DD];
#pragma unroll
        for (int r = 0; r < 8; r++) acc[r] = fmaf(w, vp[r * 32 + lane], acc[r]);
    }

    float inv = (end > beg) ? (1.f / ssum) : 0.f;
#pragma unroll
    for (int r = 0; r < 8; r++) {
        float val = acc[r] * inv + g_s[(size_t)gw * DD + r * 32 + lane];
        val = fmaxf(val, 0.f);
        g_hA[(size_t)gw * DD + r * 32 + lane] = val;
        g_hrA[(size_t)gw * DD + r * 32 + lane] = rtf32(val);
    }
}

// -------- SAGE mean aggregation: warp per node; output tf32-rounded ----------
__global__ void mean_kernel(const float* __restrict__ h)
{
    int gw = (blockIdx.x * blockDim.x + threadIdx.x) >> 5;
    int lane = threadIdx.x & 31;
    if (gw >= NN) return;
    int beg = g_rowptr[gw], end = g_rowptr[gw + 1];

    float acc[8];
#pragma unroll
    for (int r = 0; r < 8; r++) acc[r] = 0.f;
    for (int e = beg; e < end; e++) {
        int src = g_srcs[e];
        const float* hp = &h[(size_t)src * DD];
#pragma unroll
        for (int r = 0; r < 8; r++) acc[r] += hp[r * 32 + lane];
    }
    int deg = end - beg;
    float inv = 1.f / (float)(deg > 0 ? deg : 1);
#pragma unroll
    for (int r = 0; r < 8; r++)
        g_mean[(size_t)gw * DD + r * 32 + lane] = rtf32(acc[r] * inv);
}

// -------- cached fork-join resources (host objects only; no device mem) ----
static cudaStream_t g_s2 = nullptr, g_s3 = nullptr;
static cudaEvent_t  g_evF = nullptr, g_evCSR = nullptr, g_evQK = nullptr, g_evVS = nullptr;
static cudaEvent_t  g_evA[3] = {nullptr, nullptr, nullptr};
static cudaEvent_t  g_evB[3] = {nullptr, nullptr, nullptr};

// -------- launch ----------
extern "C" void kernel_launch(void* const* d_in, const int* in_sizes, int n_in,
                              void* d_out, int out_size)
{
    const float* x     = (const float*)d_in[0];
    const int*   ei    = (const int*)d_in[1];       // int32 (jax x64 disabled)
    const float* Wq    = (const float*)d_in[2];
    const float* bq    = (const float*)d_in[3];
    const float* Wk    = (const float*)d_in[4];
    const float* bk    = (const float*)d_in[5];
    const float* Wv    = (const float*)d_in[6];
    const float* bv    = (const float*)d_in[7];
    const float* Ws    = (const float*)d_in[8];
    const float* bs    = (const float*)d_in[9];
    const float* Wl    = (const float*)d_in[10];
    const float* bl    = (const float*)d_in[11];
    const float* Wr    = (const float*)d_in[12];
    const float* gamma = (const float*)d_in[13];
    const float* beta  = (const float*)d_in[14];
    const float* alpha = (const float*)d_in[15];
    float*       out   = (float*)d_out;

    float *hA, *hB, *hrA, *hrB, *wr;
    void* cntp;
    cudaGetSymbolAddress((void**)&hA,  g_hA);
    cudaGetSymbolAddress((void**)&hB,  g_hB);
    cudaGetSymbolAddress((void**)&hrA, g_hrA);
    cudaGetSymbolAddress((void**)&hrB, g_hrB);
    cudaGetSymbolAddress((void**)&wr,  g_wr);
    cudaGetSymbolAddress(&cntp,        g_cnt);

    if (g_s2 == nullptr) {
        cudaStreamCreateWithFlags(&g_s2, cudaStreamNonBlocking);
        cudaStreamCreateWithFlags(&g_s3, cudaStreamNonBlocking);
        cudaEventCreateWithFlags(&g_evF,   cudaEventDisableTiming);
        cudaEventCreateWithFlags(&g_evCSR, cudaEventDisableTiming);
        cudaEventCreateWithFlags(&g_evQK,  cudaEventDisableTiming);
        cudaEventCreateWithFlags(&g_evVS,  cudaEventDisableTiming);
        for (int i = 0; i < 3; i++) {
            cudaEventCreateWithFlags(&g_evA[i], cudaEventDisableTiming);
            cudaEventCreateWithFlags(&g_evB[i], cudaEventDisableTiming);
        }
    }

    cudaFuncSetAttribute(gemm_proj, cudaFuncAttributeMaxDynamicSharedMemorySize, SMEM_BYTES);
    cudaFuncSetAttribute(gemm_r,    cudaFuncAttributeMaxDynamicSharedMemorySize, SMEM_BYTES);
    cudaFuncSetAttribute(gemm_l,    cudaFuncAttributeMaxDynamicSharedMemorySize, SMEM_BYTES);

    const int MT = (NN + 127) / 128;   // 79
    const int PREPV = NDTOT / 4 + 10 * (WSZ / 4);

    // ---- fork: CSR chain on s3, concurrent with prep + projections ----
    cudaEventRecord(g_evF, 0);
    cudaStreamWaitEvent(g_s3, g_evF, 0);

    cudaMemsetAsync(cntp, 0, NN * sizeof(int), g_s3);
    hist_kernel<<<(EE + 255) / 256, 256, 0, g_s3>>>(ei);
    scan_kernel<<<1, 1024, 0, g_s3>>>();
    scatter_kernel<<<(EE + 255) / 256, 256, 0, g_s3>>>(ei);
    cudaEventRecord(g_evCSR, g_s3);

    // main stream: prep + Q,K projections
    round_prep<<<(PREPV + 255) / 256, 256>>>((const float4*)x,
                                             (const float4*)Wq, (const float4*)Wk,
                                             (const float4*)Wv, (const float4*)Ws,
                                             (const float4*)Wl, (const float4*)Wr);
    gemm_proj<<<dim3(MT, 4), 256, SMEM_BYTES>>>(0, bq, bk);     // q, k
    cudaEventRecord(g_evQK, 0);

    // s2: V,S projections overlap attn_logits
    cudaStreamWaitEvent(g_s2, g_evQK, 0);
    gemm_proj<<<dim3(MT, 4), 256, SMEM_BYTES, g_s2>>>(2, bv, bs);  // v, s
    cudaEventRecord(g_evVS, g_s2);

    // attn pass 1 (needs q,k + CSR)
    cudaStreamWaitEvent(0, g_evCSR, 0);
    attn_logits<<<(NN * 32 + 255) / 256, 256>>>();

    // attn pass 2 (needs logits + v,s)
    cudaStreamWaitEvent(0, g_evVS, 0);
    attn_agg<<<(NN * 32 + 255) / 256, 256>>>();

    // 3 SAGE layers: mean (s2) overlaps gemm_r (s0), then gemm_l
    float* hin  = hA;
    float* hrin = hrA;
    for (int l = 0; l < 3; l++) {
        cudaEventRecord(g_evA[l], 0);
        cudaStreamWaitEvent(g_s2, g_evA[l], 0);
        mean_kernel<<<(NN * 32 + 255) / 256, 256, 0, g_s2>>>(hin);
        cudaEventRecord(g_evB[l], g_s2);

        gemm_r<<<dim3(MT, 2), 256, SMEM_BYTES>>>(wr + (size_t)(7 + l) * WSZ, hrin);

        cudaStreamWaitEvent(0, g_evB[l], 0);

        float* hout  = (l == 2) ? out : ((l == 0) ? hB : hA);
        float* hrout = (l == 2) ? nullptr : ((hrin == hrA) ? hrB : hrA);
        gemm_l<<<dim3(MT, 2), 256, SMEM_BYTES>>>(wr + (size_t)(4 + l) * WSZ,
                                                 bl + (size_t)l * 256,
                                                 gamma + (size_t)l * 256, beta + (size_t)l * 256,
                                                 alpha, hin, hout, hrout);
        hin  = hout;
        hrin = hrout;
    }
}

// round 13
// speedup vs baseline: 1.0378x; 1.0378x over previous
#include <cuda_runtime.h>
#include <cstdint>

#define NN 10000
#define EE 320000
#define DD 256
#define NDTOT (NN*DD)
#define WSZ 65536

// -------- scratch (static device globals; no allocation) ----------
__device__ float g_q[NDTOT];
__device__ float g_k[NDTOT];
__device__ float g_v[NDTOT];
__device__ float g_s[NDTOT];
__device__ float g_hA[NDTOT];
__device__ float g_hB[NDTOT];
__device__ float g_hrA[NDTOT];    // tf32-rounded h, ping
__device__ float g_hrB[NDTOT];    // tf32-rounded h, pong
__device__ float g_xr[NDTOT];     // tf32-rounded x
__device__ float g_wr[10*WSZ];    // rounded weights: Wq,Wk,Wv,Ws,Wl0..2,Wr0..2
__device__ float g_mean[NDTOT];   // tf32-rounded at production
__device__ float g_z[NDTOT];      // partial h@Wr accumulator
__device__ float g_logits[EE];
__device__ int   g_rowptr[NN + 1];
__device__ int   g_srcs[EE];
__device__ int   g_cnt[NN];
__device__ int   g_fill[NN];

// -------- helpers ----------
__device__ __forceinline__ float rtf32(float f)
{
    uint32_t u;
    asm("cvt.rna.tf32.f32 %0, %1;" : "=r"(u) : "f"(f));
    return __uint_as_float(u);
}

__device__ __forceinline__ void mma_tf32(float* c, const uint32_t* a, const uint32_t* b)
{
    asm volatile(
        "mma.sync.aligned.m16n8k8.row.col.f32.tf32.tf32.f32 "
        "{%0,%1,%2,%3}, {%4,%5,%6,%7}, {%8,%9}, {%0,%1,%2,%3};"
        : "+f"(c[0]), "+f"(c[1]), "+f"(c[2]), "+f"(c[3])
        : "r"(a[0]), "r"(a[1]), "r"(a[2]), "r"(a[3]), "r"(b[0]), "r"(b[1]));
}

__device__ __forceinline__ void cpasync16(uint32_t dst, const void* src, int szbytes)
{
    asm volatile("cp.async.ca.shared.global [%0], [%1], 16, %2;"
                 :: "r"(dst), "l"(src), "r"(szbytes));
}
__device__ __forceinline__ void cpasync_commit() { asm volatile("cp.async.commit_group;"); }
__device__ __forceinline__ void cpasync_wait1()  { asm volatile("cp.async.wait_group 1;"); }
__device__ __forceinline__ void cpasync_wait0()  { asm volatile("cp.async.wait_group 0;"); }

// -------- prep: tf32-round x and all weights into scratch (float4) --------
__global__ void round_prep(const float4* __restrict__ x,
                           const float4* __restrict__ Wq, const float4* __restrict__ Wk,
                           const float4* __restrict__ Wv, const float4* __restrict__ Ws,
                           const float4* __restrict__ Wl, const float4* __restrict__ Wr)
{
    int i = blockIdx.x * blockDim.x + threadIdx.x;
    const int XV = NDTOT / 4;           // 640000
    const int WV = WSZ / 4;             // 16384
    const int totalv = XV + 10 * WV;
    if (i >= totalv) return;
    float4 v;
    float4* dst;
    if (i < XV) {
        v = x[i];
        dst = reinterpret_cast<float4*>(g_xr) + i;
    } else {
        int j = i - XV;
        int m = j >> 14, o = j & (WV - 1);
        const float4* src;
        if      (m == 0) src = Wq;
        else if (m == 1) src = Wk;
        else if (m == 2) src = Wv;
        else if (m == 3) src = Ws;
        else if (m <  7) src = Wl + (size_t)(m - 4) * WV;
        else             src = Wr + (size_t)(m - 7) * WV;
        v = src[o];
        dst = reinterpret_cast<float4*>(g_wr) + j;
    }
    v.x = rtf32(v.x); v.y = rtf32(v.y); v.z = rtf32(v.z); v.w = rtf32(v.w);
    *dst = v;
}

#define APAD 36
#define BPAD 136
#define ASZ (128*APAD)
#define BSZ (32*BPAD)
#define SMEM_BYTES ((2*ASZ + 2*BSZ) * 4)   // 71680

// ---- issue one chunk (A 128x32 from Asrc at col kt, B 32x128 from Bsrc) ----
#define ISSUE_CHUNK(Asrc, Bsrc, kt, buf)                                        \
    {                                                                           \
        uint32_t abase = sbase + (uint32_t)((buf) * ASZ) * 4u;                  \
        uint32_t bbase = sbase + (uint32_t)(2 * ASZ + (buf) * BSZ) * 4u;        \
        _Pragma("unroll")                                                       \
        for (int i = 0; i < 4; i++) {                                           \
            int idx = i * 256 + tid;                                            \
            int ar = idx >> 3, acq = (idx & 7) * 4;                             \
            int grow = bm + ar;                                                 \
            int sz = (grow < NN) ? 16 : 0;                                      \
            cpasync16(abase + (uint32_t)(ar * APAD + acq) * 4u,                 \
                      (Asrc) + (size_t)grow * DD + (kt) + acq, sz);             \
        }                                                                       \
        _Pragma("unroll")                                                       \
        for (int i = 0; i < 4; i++) {                                           \
            int idx = i * 256 + tid;                                            \
            int br = idx >> 5, bcq = (idx & 31) * 4;                            \
            cpasync16(bbase + (uint32_t)(br * BPAD + bcq) * 4u,                 \
                      (Bsrc) + (size_t)((kt) + br) * DD + bn + bcq, 16);        \
        }                                                                       \
        cpasync_commit();                                                       \
    }

#define COMPUTE_CHUNK(buf)                                                      \
    {                                                                           \
        const float* pA = s_dyn + (buf) * ASZ;                                  \
        const float* pB = s_dyn + 2 * ASZ + (buf) * BSZ;                        \
        _Pragma("unroll")                                                       \
        for (int k8 = 0; k8 < 4; k8++) {                                        \
            const int kb = k8 * 8;                                              \
            uint32_t af[4][4], bf[4][2];                                        \
            _Pragma("unroll")                                                   \
            for (int mt = 0; mt < 4; mt++) {                                    \
                int mr = wm + mt * 16 + fr;                                     \
                af[mt][0] = __float_as_uint(pA[mr * APAD + kb + fc]);           \
                af[mt][1] = __float_as_uint(pA[(mr + 8) * APAD + kb + fc]);     \
                af[mt][2] = __float_as_uint(pA[mr * APAD + kb + fc + 4]);       \
                af[mt][3] = __float_as_uint(pA[(mr + 8) * APAD + kb + fc + 4]); \
            }                                                                   \
            _Pragma("unroll")                                                   \
            for (int nt = 0; nt < 4; nt++) {                                    \
                int nc = wn + nt * 8 + fr;                                      \
                bf[nt][0] = __float_as_uint(pB[(kb + fc) * BPAD + nc]);         \
                bf[nt][1] = __float_as_uint(pB[(kb + fc + 4) * BPAD + nc]);     \
            }                                                                   \
            _Pragma("unroll")                                                   \
            for (int mt = 0; mt < 4; mt++)                                      \
                _Pragma("unroll")                                               \
                for (int nt = 0; nt < 4; nt++)                                  \
                    mma_tf32(acc[mt][nt], af[mt], bf[nt]);                      \
        }                                                                       \
    }

#define GEMM_PROLOGUE()                                                         \
    extern __shared__ float s_dyn[];                                            \
    const uint32_t sbase = (uint32_t)__cvta_generic_to_shared(s_dyn);           \
    const int tid  = threadIdx.x;                                               \
    const int lane = tid & 31;                                                  \
    const int warp = tid >> 5;                                                  \
    const int wm = (warp >> 2) * 64;                                            \
    const int wn = (warp & 3) * 32;                                             \
    const int fr = lane >> 2;                                                   \
    const int fc = lane & 3;                                                    \
    const int bm = blockIdx.x * 128;                                            \
    float acc[4][4][4];                                                         \
    _Pragma("unroll")                                                           \
    for (int mt = 0; mt < 4; mt++)                                              \
        _Pragma("unroll")                                                       \
        for (int nt = 0; nt < 4; nt++)                                          \
            _Pragma("unroll")                                                   \
            for (int r = 0; r < 4; r++) acc[mt][nt][r] = 0.f;

#define GEMM_MAINLOOP(Asrc, Bsrc)                                               \
    {                                                                           \
        const int NC = 8;                                                       \
        ISSUE_CHUNK(Asrc, Bsrc, 0, 0);                                          \
        ISSUE_CHUNK(Asrc, Bsrc, 32, 1);                                         \
        for (int c = 0; c < NC; c++) {                                          \
            if (c + 1 < NC) cpasync_wait1(); else cpasync_wait0();              \
            __syncthreads();                                                    \
            COMPUTE_CHUNK(c & 1);                                               \
            __syncthreads();                                                    \
            if (c + 2 < NC) ISSUE_CHUNK(Asrc, Bsrc, (c + 2) * 32, c & 1);       \
        }                                                                       \
    }

// =====================================================================
// Fused QKVS projection: A = g_xr (pre-rounded), B = g_wr[mat]
// grid (79, 8): blockIdx.y>>1 selects matrix, &1 selects N-half.
// =====================================================================
__global__ void __launch_bounds__(256, 2)
gemm_qkvs(const float* __restrict__ bq, const float* __restrict__ bk,
          const float* __restrict__ bv, const float* __restrict__ bs)
{
    GEMM_PROLOGUE();
    const int mat = blockIdx.y >> 1;
    const int bn  = (blockIdx.y & 1) * 128;

    const float* B = g_wr + (size_t)mat * WSZ;
    const float* bias; float* C;
    if      (mat == 0) { bias = bq; C = g_q; }
    else if (mat == 1) { bias = bk; C = g_k; }
    else if (mat == 2) { bias = bv; C = g_v; }
    else               { bias = bs; C = g_s; }

    GEMM_MAINLOOP(g_xr, B);

    float bb[4][2];
#pragma unroll
    for (int nt = 0; nt < 4; nt++) {
        int col = bn + wn + nt * 8 + fc * 2;
        bb[nt][0] = bias[col]; bb[nt][1] = bias[col + 1];
    }
#pragma unroll
    for (int mt = 0; mt < 4; mt++) {
#pragma unroll
        for (int nt = 0; nt < 4; nt++) {
            int row = bm + wm + mt * 16 + fr;
            int col = bn + wn + nt * 8 + fc * 2;
            if (row < NN) {
                float2 o = make_float2(acc[mt][nt][0] + bb[nt][0], acc[mt][nt][1] + bb[nt][1]);
                *reinterpret_cast<float2*>(&C[(size_t)row * DD + col]) = o;
            }
            if (row + 8 < NN) {
                float2 o = make_float2(acc[mt][nt][2] + bb[nt][0], acc[mt][nt][3] + bb[nt][1]);
                *reinterpret_cast<float2*>(&C[(size_t)(row + 8) * DD + col]) = o;
            }
        }
    }
}

// =====================================================================
// SAGE half 1: g_z = hr_in @ Wr   (no epilogue; runs concurrent w/ mean)
// =====================================================================
__global__ void __launch_bounds__(256, 2)
gemm_r(const float* __restrict__ Br, const float* __restrict__ hr_in)
{
    GEMM_PROLOGUE();
    const int bn = blockIdx.y * 128;

    GEMM_MAINLOOP(hr_in, Br);

#pragma unroll
    for (int mt = 0; mt < 4; mt++) {
#pragma unroll
        for (int nt = 0; nt < 4; nt++) {
            int row = bm + wm + mt * 16 + fr;
            int col = bn + wn + nt * 8 + fc * 2;
            if (row < NN)
                *reinterpret_cast<float2*>(&g_z[(size_t)row * DD + col]) =
                    make_float2(acc[mt][nt][0], acc[mt][nt][1]);
            if (row + 8 < NN)
                *reinterpret_cast<float2*>(&g_z[(size_t)(row + 8) * DD + col]) =
                    make_float2(acc[mt][nt][2], acc[mt][nt][3]);
        }
    }
}

// =====================================================================
// SAGE half 2: acc = g_mean @ Wl; epilogue adds g_z + bl, BN + gated
// residual (full-precision hin) + relu -> hout (+ rounded hr_out)
// =====================================================================
__global__ void __launch_bounds__(256, 2)
gemm_l(const float* __restrict__ Bl, const float* __restrict__ bl,
       const float* __restrict__ gamma, const float* __restrict__ beta,
       const float* __restrict__ alpha,
       const float* __restrict__ hin,
       float* __restrict__ hout, float* __restrict__ hr_out)
{
    GEMM_PROLOGUE();
    const int bn = blockIdx.y * 128;

    GEMM_MAINLOOP(g_mean, Bl);

    const float al  = 1.f / (1.f + __expf(-alpha[0]));
    const float oma = 1.f - al;
    const float BNS = 0.9999950000374994f;   // 1/sqrt(1+1e-5)

    float blv[4][2], gv[4][2], bev[4][2];
#pragma unroll
    for (int nt = 0; nt < 4; nt++) {
        int col = bn + wn + nt * 8 + fc * 2;
        blv[nt][0] = bl[col];    blv[nt][1] = bl[col + 1];
        gv[nt][0]  = gamma[col]; gv[nt][1]  = gamma[col + 1];
        bev[nt][0] = beta[col];  bev[nt][1] = beta[col + 1];
    }

#pragma unroll
    for (int mt = 0; mt < 4; mt++) {
#pragma unroll
        for (int nt = 0; nt < 4; nt++) {
            int row = bm + wm + mt * 16 + fr;
            int col = bn + wn + nt * 8 + fc * 2;
#pragma unroll
            for (int h = 0; h < 2; h++) {
                int rr = row + h * 8;
                if (rr < NN) {
                    float2 zr = *reinterpret_cast<const float2*>(&g_z[(size_t)rr * DD + col]);
                    float2 rv = *reinterpret_cast<const float2*>(&hin[(size_t)rr * DD + col]);
                    float z0 = fmaf((acc[mt][nt][h*2]   + zr.x + blv[nt][0]) * BNS, gv[nt][0], bev[nt][0]);
                    float z1 = fmaf((acc[mt][nt][h*2+1] + zr.y + blv[nt][1]) * BNS, gv[nt][1], bev[nt][1]);
                    float o0 = fmaxf(fmaf(al, z0, oma * rv.x), 0.f);
                    float o1 = fmaxf(fmaf(al, z1, oma * rv.y), 0.f);
                    *reinterpret_cast<float2*>(&hout[(size_t)rr * DD + col]) = make_float2(o0, o1);
                    if (hr_out) {
                        *reinterpret_cast<float2*>(&hr_out[(size_t)rr * DD + col]) =
                            make_float2(rtf32(o0), rtf32(o1));
                    }
                }
            }
        }
    }
}

// -------- CSR build ----------
__global__ void hist_kernel(const int* __restrict__ ei)
{
    int e = blockIdx.x * blockDim.x + threadIdx.x;
    if (e >= EE) return;
    atomicAdd(&g_cnt[ei[EE + e]], 1);
}

// coalesced smem-staged block scan: 1024 threads x 10 elems
__global__ void scan_kernel()
{
    __shared__ int sh[10240];          // 40 KB
    __shared__ int wsum[32];
    const int tid = threadIdx.x;
    const int lane = tid & 31, wid = tid >> 5;
    const int PER = 10;

    for (int i = tid; i < 10240; i += 1024)
        sh[i] = (i < NN) ? g_cnt[i] : 0;
    __syncthreads();

    int base = tid * PER;
    int loc[PER];
    int s = 0;
#pragma unroll
    for (int j = 0; j < PER; j++) {
        s += sh[base + j];
        loc[j] = s;
    }
    int ssum = s;
#pragma unroll
    for (int off = 1; off < 32; off <<= 1) {
        int t = __shfl_up_sync(0xffffffffu, ssum, off);
        if (lane >= off) ssum += t;
    }
    if (lane == 31) wsum[wid] = ssum;
    __syncthreads();
    if (wid == 0) {
        int w = wsum[lane];
#pragma unroll
        for (int off = 1; off < 32; off <<= 1) {
            int t = __shfl_up_sync(0xffffffffu, w, off);
            if (lane >= off) w += t;
        }
        wsum[lane] = w;
    }
    __syncthreads();

    int offset = ssum - s + (wid > 0 ? wsum[wid - 1] : 0);
#pragma unroll
    for (int j = 0; j < PER; j++)
        sh[base + j] = offset + loc[j];
    __syncthreads();

    if (tid == 0) { g_rowptr[0] = 0; g_fill[0] = 0; }
    for (int i = tid; i < NN; i += 1024) {
        int incl = sh[i];
        g_rowptr[i + 1] = incl;
        if (i > 0) g_fill[i] = sh[i - 1];
    }
}

__global__ void scatter_kernel(const int* __restrict__ ei)
{
    int e = blockIdx.x * blockDim.x + threadIdx.x;
    if (e >= EE) return;
    int src = ei[e];
    int dst = ei[EE + e];
    int pos = atomicAdd(&g_fill[dst], 1);
    g_srcs[pos] = src;
}

// -------- TransformerConv: warp per node, 2-pass softmax aggregation ----------
__global__ void attn_kernel()
{
    int gw = (blockIdx.x * blockDim.x + threadIdx.x) >> 5;
    int lane = threadIdx.x & 31;
    if (gw >= NN) return;
    int beg = g_rowptr[gw], end = g_rowptr[gw + 1];

    float qr[8];
#pragma unroll
    for (int r = 0; r < 8; r++) qr[r] = g_q[(size_t)gw * DD + r * 32 + lane];

    float m = -1e30f;
    for (int e = beg; e < end; e++) {
        int src = g_srcs[e];
        const float* kp = &g_k[(size_t)src * DD];
        float p = 0.f;
#pragma unroll
        for (int r = 0; r < 8; r++) p = fmaf(qr[r], kp[r * 32 + lane], p);
#pragma unroll
        for (int off = 16; off; off >>= 1) p += __shfl_xor_sync(0xffffffffu, p, off);
        p *= 0.0625f;
        if (lane == 0) g_logits[e] = p;
        m = fmaxf(m, p);
    }

    float acc[8];
#pragma unroll
    for (int r = 0; r < 8; r++) acc[r] = 0.f;
    float ssum = 0.f;
    for (int e = beg; e < end; e++) {
        int src = g_srcs[e];
        float w = __expf(g_logits[e] - m);
        ssum += w;
        const float* vp = &g_v[(size_t)src * DD];
#pragma unroll
        for (int r = 0; r < 8; r++) acc[r] = fmaf(w, vp[r * 32 + lane], acc[r]);
    }

    float inv = (end > beg) ? (1.f / ssum) : 0.f;
#pragma unroll
    for (int r = 0; r < 8; r++) {
        float val = acc[r] * inv + g_s[(size_t)gw * DD + r * 32 + lane];
        val = fmaxf(val, 0.f);
        g_hA[(size_t)gw * DD + r * 32 + lane] = val;
        g_hrA[(size_t)gw * DD + r * 32 + lane] = rtf32(val);
    }
}

// -------- SAGE mean aggregation: warp per node; output tf32-rounded ----------
__global__ void mean_kernel(const float* __restrict__ h)
{
    int gw = (blockIdx.x * blockDim.x + threadIdx.x) >> 5;
    int lane = threadIdx.x & 31;
    if (gw >= NN) return;
    int beg = g_rowptr[gw], end = g_rowptr[gw + 1];

    float acc[8];
#pragma unroll
    for (int r = 0; r < 8; r++) acc[r] = 0.f;
    for (int e = beg; e < end; e++) {
        int src = g_srcs[e];
        const float* hp = &h[(size_t)src * DD];
#pragma unroll
        for (int r = 0; r < 8; r++) acc[r] += hp[r * 32 + lane];
    }
    int deg = end - beg;
    float inv = 1.f / (float)(deg > 0 ? deg : 1);
#pragma unroll
    for (int r = 0; r < 8; r++)
        g_mean[(size_t)gw * DD + r * 32 + lane] = rtf32(acc[r] * inv);
}

// -------- cached fork-join resources (host objects only; no device mem) ----
static cudaStream_t g_s2 = nullptr;
static cudaEvent_t  g_evF = nullptr, g_evJ = nullptr;
static cudaEvent_t  g_evA[3] = {nullptr, nullptr, nullptr};
static cudaEvent_t  g_evB[3] = {nullptr, nullptr, nullptr};

// -------- launch ----------
extern "C" void kernel_launch(void* const* d_in, const int* in_sizes, int n_in,
                              void* d_out, int out_size)
{
    const float* x     = (const float*)d_in[0];
    const int*   ei    = (const int*)d_in[1];       // int32 (jax x64 disabled)
    const float* Wq    = (const float*)d_in[2];
    const float* bq    = (const float*)d_in[3];
    const float* Wk    = (const float*)d_in[4];
    const float* bk    = (const float*)d_in[5];
    const float* Wv    = (const float*)d_in[6];
    const float* bv    = (const float*)d_in[7];
    const float* Ws    = (const float*)d_in[8];
    const float* bs    = (const float*)d_in[9];
    const float* Wl    = (const float*)d_in[10];
    const float* bl    = (const float*)d_in[11];
    const float* Wr    = (const float*)d_in[12];
    const float* gamma = (const float*)d_in[13];
    const float* beta  = (const float*)d_in[14];
    const float* alpha = (const float*)d_in[15];
    float*       out   = (float*)d_out;

    float *hA, *hB, *hrA, *hrB, *wr;
    void* cntp;
    cudaGetSymbolAddress((void**)&hA,  g_hA);
    cudaGetSymbolAddress((void**)&hB,  g_hB);
    cudaGetSymbolAddress((void**)&hrA, g_hrA);
    cudaGetSymbolAddress((void**)&hrB, g_hrB);
    cudaGetSymbolAddress((void**)&wr,  g_wr);
    cudaGetSymbolAddress(&cntp,        g_cnt);

    if (g_s2 == nullptr) {
        cudaStreamCreateWithFlags(&g_s2, cudaStreamNonBlocking);
        cudaEventCreateWithFlags(&g_evF, cudaEventDisableTiming);
        cudaEventCreateWithFlags(&g_evJ, cudaEventDisableTiming);
        for (int i = 0; i < 3; i++) {
            cudaEventCreateWithFlags(&g_evA[i], cudaEventDisableTiming);
            cudaEventCreateWithFlags(&g_evB[i], cudaEventDisableTiming);
        }
    }

    cudaFuncSetAttribute(gemm_qkvs, cudaFuncAttributeMaxDynamicSharedMemorySize, SMEM_BYTES);
    cudaFuncSetAttribute(gemm_r,    cudaFuncAttributeMaxDynamicSharedMemorySize, SMEM_BYTES);
    cudaFuncSetAttribute(gemm_l,    cudaFuncAttributeMaxDynamicSharedMemorySize, SMEM_BYTES);

    const int MT = (NN + 127) / 128;   // 79
    const int PREPV = NDTOT / 4 + 10 * (WSZ / 4);

    // ---- fork: CSR chain on g_s2, concurrent with prep + QKVS ----
    cudaEventRecord(g_evF, 0);
    cudaStreamWaitEvent(g_s2, g_evF, 0);

    cudaMemsetAsync(cntp, 0, NN * sizeof(int), g_s2);
    hist_kernel<<<(EE + 255) / 256, 256, 0, g_s2>>>(ei);
    scan_kernel<<<1, 1024, 0, g_s2>>>();
    scatter_kernel<<<(EE + 255) / 256, 256, 0, g_s2>>>(ei);

    // main stream: prep (float4) + fused projections
    round_prep<<<(PREPV + 255) / 256, 256>>>((const float4*)x,
                                             (const float4*)Wq, (const float4*)Wk,
                                             (const float4*)Wv, (const float4*)Ws,
                                             (const float4*)Wl, (const float4*)Wr);
    gemm_qkvs<<<dim3(MT, 8), 256, SMEM_BYTES>>>(bq, bk, bv, bs);

    // ---- join ----
    cudaEventRecord(g_evJ, g_s2);
    cudaStreamWaitEvent(0, g_evJ, 0);

    // TransformerConv
    attn_kernel<<<(NN * 32 + 255) / 256, 256>>>();

    // 3 SAGE layers: mean (stream2) overlaps gemm_r (stream0), then gemm_l
    float* hin  = hA;
    float* hrin = hrA;
    for (int l = 0; l < 3; l++) {
        cudaEventRecord(g_evA[l], 0);
        cudaStreamWaitEvent(g_s2, g_evA[l], 0);
        mean_kernel<<<(NN * 32 + 255) / 256, 256, 0, g_s2>>>(hin);
        cudaEventRecord(g_evB[l], g_s2);

        gemm_r<<<dim3(MT, 2), 256, SMEM_BYTES>>>(wr + (size_t)(7 + l) * WSZ, hrin);

        cudaStreamWaitEvent(0, g_evB[l], 0);

        float* hout  = (l == 2) ? out : ((l == 0) ? hB : hA);
        float* hrout = (l == 2) ? nullptr : ((hrin == hrA) ? hrB : hrA);
        gemm_l<<<dim3(MT, 2), 256, SMEM_BYTES>>>(wr + (size_t)(4 + l) * WSZ,
                                                 bl + (size_t)l * 256,
                                                 gamma + (size_t)l * 256, beta + (size_t)l * 256,
                                                 alpha, hin, hout, hrout);
        hin  = hout;
        hrin = hrout;
    }
}

// round 14
// speedup vs baseline: 1.0452x; 1.0071x over previous
#include <cuda_runtime.h>
#include <cstdint>

#define NN 10000
#define EE 320000
#define DD 256
#define NDTOT (NN*DD)
#define WSZ 65536

// -------- scratch (static device globals; no allocation) ----------
__device__ float g_q[NDTOT];
__device__ float g_k[NDTOT];
__device__ float g_v[NDTOT];
__device__ float g_s[NDTOT];
__device__ float g_hA[NDTOT];
__device__ float g_hB[NDTOT];
__device__ float g_hrA[NDTOT];    // tf32-rounded h, ping
__device__ float g_hrB[NDTOT];    // tf32-rounded h, pong
__device__ float g_xr[NDTOT];     // tf32-rounded x
__device__ float g_wr[10*WSZ];    // rounded weights: Wq,Wk,Wv,Ws,Wl0..2,Wr0..2
__device__ float g_mean[NDTOT];   // tf32-rounded at production
__device__ float g_z[NDTOT];      // partial h@Wr accumulator
__device__ float g_logits[EE];
__device__ int   g_rowptr[NN + 1];
__device__ int   g_srcs[EE];
__device__ int   g_cnt[NN];
__device__ int   g_fill[NN];

// -------- helpers ----------
__device__ __forceinline__ float rtf32(float f)
{
    uint32_t u;
    asm("cvt.rna.tf32.f32 %0, %1;" : "=r"(u) : "f"(f));
    return __uint_as_float(u);
}

__device__ __forceinline__ void mma_tf32(float* c, const uint32_t* a, const uint32_t* b)
{
    asm volatile(
        "mma.sync.aligned.m16n8k8.row.col.f32.tf32.tf32.f32 "
        "{%0,%1,%2,%3}, {%4,%5,%6,%7}, {%8,%9}, {%0,%1,%2,%3};"
        : "+f"(c[0]), "+f"(c[1]), "+f"(c[2]), "+f"(c[3])
        : "r"(a[0]), "r"(a[1]), "r"(a[2]), "r"(a[3]), "r"(b[0]), "r"(b[1]));
}

__device__ __forceinline__ void cpasync16(uint32_t dst, const void* src, int szbytes)
{
    asm volatile("cp.async.ca.shared.global [%0], [%1], 16, %2;"
                 :: "r"(dst), "l"(src), "r"(szbytes));
}
__device__ __forceinline__ void cpasync_commit() { asm volatile("cp.async.commit_group;"); }
__device__ __forceinline__ void cpasync_wait1()  { asm volatile("cp.async.wait_group 1;"); }
__device__ __forceinline__ void cpasync_wait0()  { asm volatile("cp.async.wait_group 0;"); }

// -------- prep: tf32-round x and all weights into scratch (float4) --------
__global__ void round_prep(const float4* __restrict__ x,
                           const float4* __restrict__ Wq, const float4* __restrict__ Wk,
                           const float4* __restrict__ Wv, const float4* __restrict__ Ws,
                           const float4* __restrict__ Wl, const float4* __restrict__ Wr)
{
    int i = blockIdx.x * blockDim.x + threadIdx.x;
    const int XV = NDTOT / 4;           // 640000
    const int WV = WSZ / 4;             // 16384
    const int totalv = XV + 10 * WV;
    if (i >= totalv) return;
    float4 v;
    float4* dst;
    if (i < XV) {
        v = x[i];
        dst = reinterpret_cast<float4*>(g_xr) + i;
    } else {
        int j = i - XV;
        int m = j >> 14, o = j & (WV - 1);
        const float4* src;
        if      (m == 0) src = Wq;
        else if (m == 1) src = Wk;
        else if (m == 2) src = Wv;
        else if (m == 3) src = Ws;
        else if (m <  7) src = Wl + (size_t)(m - 4) * WV;
        else             src = Wr + (size_t)(m - 7) * WV;
        v = src[o];
        dst = reinterpret_cast<float4*>(g_wr) + j;
    }
    v.x = rtf32(v.x); v.y = rtf32(v.y); v.z = rtf32(v.z); v.w = rtf32(v.w);
    *dst = v;
}

#define APAD 36
#define BPAD 136
#define ASZ (128*APAD)
#define BSZ (32*BPAD)
#define SMEM_BYTES ((2*ASZ + 2*BSZ) * 4)   // 71680

// ---- issue one chunk (A 128x32 from Asrc at col kt, B 32x128 from Bsrc) ----
#define ISSUE_CHUNK(Asrc, Bsrc, kt, buf)                                        \
    {                                                                           \
        uint32_t abase = sbase + (uint32_t)((buf) * ASZ) * 4u;                  \
        uint32_t bbase = sbase + (uint32_t)(2 * ASZ + (buf) * BSZ) * 4u;        \
        _Pragma("unroll")                                                       \
        for (int i = 0; i < 4; i++) {                                           \
            int idx = i * 256 + tid;                                            \
            int ar = idx >> 3, acq = (idx & 7) * 4;                             \
            int grow = bm + ar;                                                 \
            int sz = (grow < NN) ? 16 : 0;                                      \
            cpasync16(abase + (uint32_t)(ar * APAD + acq) * 4u,                 \
                      (Asrc) + (size_t)grow * DD + (kt) + acq, sz);             \
        }                                                                       \
        _Pragma("unroll")                                                       \
        for (int i = 0; i < 4; i++) {                                           \
            int idx = i * 256 + tid;                                            \
            int br = idx >> 5, bcq = (idx & 31) * 4;                            \
            cpasync16(bbase + (uint32_t)(br * BPAD + bcq) * 4u,                 \
                      (Bsrc) + (size_t)((kt) + br) * DD + bn + bcq, 16);        \
        }                                                                       \
        cpasync_commit();                                                       \
    }

#define COMPUTE_CHUNK(buf)                                                      \
    {                                                                           \
        const float* pA = s_dyn + (buf) * ASZ;                                  \
        const float* pB = s_dyn + 2 * ASZ + (buf) * BSZ;                        \
        _Pragma("unroll")                                                       \
        for (int k8 = 0; k8 < 4; k8++) {                                        \
            const int kb = k8 * 8;                                              \
            uint32_t af[4][4], bf[4][2];                                        \
            _Pragma("unroll")                                                   \
            for (int mt = 0; mt < 4; mt++) {                                    \
                int mr = wm + mt * 16 + fr;                                     \
                af[mt][0] = __float_as_uint(pA[mr * APAD + kb + fc]);           \
                af[mt][1] = __float_as_uint(pA[(mr + 8) * APAD + kb + fc]);     \
                af[mt][2] = __float_as_uint(pA[mr * APAD + kb + fc + 4]);       \
                af[mt][3] = __float_as_uint(pA[(mr + 8) * APAD + kb + fc + 4]); \
            }                                                                   \
            _Pragma("unroll")                                                   \
            for (int nt = 0; nt < 4; nt++) {                                    \
                int nc = wn + nt * 8 + fr;                                      \
                bf[nt][0] = __float_as_uint(pB[(kb + fc) * BPAD + nc]);         \
                bf[nt][1] = __float_as_uint(pB[(kb + fc + 4) * BPAD + nc]);     \
            }                                                                   \
            _Pragma("unroll")                                                   \
            for (int mt = 0; mt < 4; mt++)                                      \
                _Pragma("unroll")                                               \
                for (int nt = 0; nt < 4; nt++)                                  \
                    mma_tf32(acc[mt][nt], af[mt], bf[nt]);                      \
        }                                                                       \
    }

#define GEMM_PROLOGUE()                                                         \
    extern __shared__ float s_dyn[];                                            \
    const uint32_t sbase = (uint32_t)__cvta_generic_to_shared(s_dyn);           \
    const int tid  = threadIdx.x;                                               \
    const int lane = tid & 31;                                                  \
    const int warp = tid >> 5;                                                  \
    const int wm = (warp >> 2) * 64;                                            \
    const int wn = (warp & 3) * 32;                                             \
    const int fr = lane >> 2;                                                   \
    const int fc = lane & 3;                                                    \
    const int bm = blockIdx.x * 128;                                            \
    float acc[4][4][4];                                                         \
    _Pragma("unroll")                                                           \
    for (int mt = 0; mt < 4; mt++)                                              \
        _Pragma("unroll")                                                       \
        for (int nt = 0; nt < 4; nt++)                                          \
            _Pragma("unroll")                                                   \
            for (int r = 0; r < 4; r++) acc[mt][nt][r] = 0.f;

#define GEMM_MAINLOOP(Asrc, Bsrc)                                               \
    {                                                                           \
        const int NC = 8;                                                       \
        ISSUE_CHUNK(Asrc, Bsrc, 0, 0);                                          \
        ISSUE_CHUNK(Asrc, Bsrc, 32, 1);                                         \
        for (int c = 0; c < NC; c++) {                                          \
            if (c + 1 < NC) cpasync_wait1(); else cpasync_wait0();              \
            __syncthreads();                                                    \
            COMPUTE_CHUNK(c & 1);                                               \
            __syncthreads();                                                    \
            if (c + 2 < NC) ISSUE_CHUNK(Asrc, Bsrc, (c + 2) * 32, c & 1);       \
        }                                                                       \
    }

// =====================================================================
// Fused QKVS projection: A = g_xr (pre-rounded), B = g_wr[mat]
// grid (79, 8): blockIdx.y>>1 selects matrix, &1 selects N-half.
// =====================================================================
__global__ void __launch_bounds__(256, 2)
gemm_qkvs(const float* __restrict__ bq, const float* __restrict__ bk,
          const float* __restrict__ bv, const float* __restrict__ bs)
{
    GEMM_PROLOGUE();
    const int mat = blockIdx.y >> 1;
    const int bn  = (blockIdx.y & 1) * 128;

    const float* B = g_wr + (size_t)mat * WSZ;
    const float* bias; float* C;
    if      (mat == 0) { bias = bq; C = g_q; }
    else if (mat == 1) { bias = bk; C = g_k; }
    else if (mat == 2) { bias = bv; C = g_v; }
    else               { bias = bs; C = g_s; }

    GEMM_MAINLOOP(g_xr, B);

    float bb[4][2];
#pragma unroll
    for (int nt = 0; nt < 4; nt++) {
        int col = bn + wn + nt * 8 + fc * 2;
        bb[nt][0] = bias[col]; bb[nt][1] = bias[col + 1];
    }
#pragma unroll
    for (int mt = 0; mt < 4; mt++) {
#pragma unroll
        for (int nt = 0; nt < 4; nt++) {
            int row = bm + wm + mt * 16 + fr;
            int col = bn + wn + nt * 8 + fc * 2;
            if (row < NN) {
                float2 o = make_float2(acc[mt][nt][0] + bb[nt][0], acc[mt][nt][1] + bb[nt][1]);
                *reinterpret_cast<float2*>(&C[(size_t)row * DD + col]) = o;
            }
            if (row + 8 < NN) {
                float2 o = make_float2(acc[mt][nt][2] + bb[nt][0], acc[mt][nt][3] + bb[nt][1]);
                *reinterpret_cast<float2*>(&C[(size_t)(row + 8) * DD + col]) = o;
            }
        }
    }
}

// =====================================================================
// SAGE half 1: g_z = hr_in @ Wr   (no epilogue; runs concurrent w/ mean)
// =====================================================================
__global__ void __launch_bounds__(256, 2)
gemm_r(const float* __restrict__ Br, const float* __restrict__ hr_in)
{
    GEMM_PROLOGUE();
    const int bn = blockIdx.y * 128;

    GEMM_MAINLOOP(hr_in, Br);

#pragma unroll
    for (int mt = 0; mt < 4; mt++) {
#pragma unroll
        for (int nt = 0; nt < 4; nt++) {
            int row = bm + wm + mt * 16 + fr;
            int col = bn + wn + nt * 8 + fc * 2;
            if (row < NN)
                *reinterpret_cast<float2*>(&g_z[(size_t)row * DD + col]) =
                    make_float2(acc[mt][nt][0], acc[mt][nt][1]);
            if (row + 8 < NN)
                *reinterpret_cast<float2*>(&g_z[(size_t)(row + 8) * DD + col]) =
                    make_float2(acc[mt][nt][2], acc[mt][nt][3]);
        }
    }
}

// =====================================================================
// SAGE half 2: acc = g_mean @ Wl; epilogue adds g_z + bl, BN + gated
// residual (full-precision hin) + relu -> hout (+ rounded hr_out)
// =====================================================================
__global__ void __launch_bounds__(256, 2)
gemm_l(const float* __restrict__ Bl, const float* __restrict__ bl,
       const float* __restrict__ gamma, const float* __restrict__ beta,
       const float* __restrict__ alpha,
       const float* __restrict__ hin,
       float* __restrict__ hout, float* __restrict__ hr_out)
{
    GEMM_PROLOGUE();
    const int bn = blockIdx.y * 128;

    GEMM_MAINLOOP(g_mean, Bl);

    const float al  = 1.f / (1.f + __expf(-alpha[0]));
    const float oma = 1.f - al;
    const float BNS = 0.9999950000374994f;   // 1/sqrt(1+1e-5)

    float blv[4][2], gv[4][2], bev[4][2];
#pragma unroll
    for (int nt = 0; nt < 4; nt++) {
        int col = bn + wn + nt * 8 + fc * 2;
        blv[nt][0] = bl[col];    blv[nt][1] = bl[col + 1];
        gv[nt][0]  = gamma[col]; gv[nt][1]  = gamma[col + 1];
        bev[nt][0] = beta[col];  bev[nt][1] = beta[col + 1];
    }

#pragma unroll
    for (int mt = 0; mt < 4; mt++) {
#pragma unroll
        for (int nt = 0; nt < 4; nt++) {
            int row = bm + wm + mt * 16 + fr;
            int col = bn + wn + nt * 8 + fc * 2;
#pragma unroll
            for (int h = 0; h < 2; h++) {
                int rr = row + h * 8;
                if (rr < NN) {
                    float2 zr = *reinterpret_cast<const float2*>(&g_z[(size_t)rr * DD + col]);
                    float2 rv = *reinterpret_cast<const float2*>(&hin[(size_t)rr * DD + col]);
                    float z0 = fmaf((acc[mt][nt][h*2]   + zr.x + blv[nt][0]) * BNS, gv[nt][0], bev[nt][0]);
                    float z1 = fmaf((acc[mt][nt][h*2+1] + zr.y + blv[nt][1]) * BNS, gv[nt][1], bev[nt][1]);
                    float o0 = fmaxf(fmaf(al, z0, oma * rv.x), 0.f);
                    float o1 = fmaxf(fmaf(al, z1, oma * rv.y), 0.f);
                    *reinterpret_cast<float2*>(&hout[(size_t)rr * DD + col]) = make_float2(o0, o1);
                    if (hr_out) {
                        *reinterpret_cast<float2*>(&hr_out[(size_t)rr * DD + col]) =
                            make_float2(rtf32(o0), rtf32(o1));
                    }
                }
            }
        }
    }
}

// -------- CSR build ----------
__global__ void hist_kernel(const int* __restrict__ ei)
{
    int e = blockIdx.x * blockDim.x + threadIdx.x;
    if (e >= EE) return;
    atomicAdd(&g_cnt[ei[EE + e]], 1);
}

// coalesced smem-staged block scan: 1024 threads x 10 elems
__global__ void scan_kernel()
{
    __shared__ int sh[10240];          // 40 KB
    __shared__ int wsum[32];
    const int tid = threadIdx.x;
    const int lane = tid & 31, wid = tid >> 5;
    const int PER = 10;

    for (int i = tid; i < 10240; i += 1024)
        sh[i] = (i < NN) ? g_cnt[i] : 0;
    __syncthreads();

    int base = tid * PER;
    int loc[PER];
    int s = 0;
#pragma unroll
    for (int j = 0; j < PER; j++) {
        s += sh[base + j];
        loc[j] = s;
    }
    int ssum = s;
#pragma unroll
    for (int off = 1; off < 32; off <<= 1) {
        int t = __shfl_up_sync(0xffffffffu, ssum, off);
        if (lane >= off) ssum += t;
    }
    if (lane == 31) wsum[wid] = ssum;
    __syncthreads();
    if (wid == 0) {
        int w = wsum[lane];
#pragma unroll
        for (int off = 1; off < 32; off <<= 1) {
            int t = __shfl_up_sync(0xffffffffu, w, off);
            if (lane >= off) w += t;
        }
        wsum[lane] = w;
    }
    __syncthreads();

    int offset = ssum - s + (wid > 0 ? wsum[wid - 1] : 0);
#pragma unroll
    for (int j = 0; j < PER; j++)
        sh[base + j] = offset + loc[j];
    __syncthreads();

    if (tid == 0) { g_rowptr[0] = 0; g_fill[0] = 0; }
    for (int i = tid; i < NN; i += 1024) {
        int incl = sh[i];
        g_rowptr[i + 1] = incl;
        if (i > 0) g_fill[i] = sh[i - 1];
    }
}

__global__ void scatter_kernel(const int* __restrict__ ei)
{
    int e = blockIdx.x * blockDim.x + threadIdx.x;
    if (e >= EE) return;
    int src = ei[e];
    int dst = ei[EE + e];
    int pos = atomicAdd(&g_fill[dst], 1);
    g_srcs[pos] = src;
}

// -------- TransformerConv: warp per node, 2-pass softmax aggregation ----------
__global__ void attn_kernel()
{
    int gw = (blockIdx.x * blockDim.x + threadIdx.x) >> 5;
    int lane = threadIdx.x & 31;
    if (gw >= NN) return;
    int beg = g_rowptr[gw], end = g_rowptr[gw + 1];

    float qr[8];
#pragma unroll
    for (int r = 0; r < 8; r++) qr[r] = g_q[(size_t)gw * DD + r * 32 + lane];

    float m = -1e30f;
    for (int e = beg; e < end; e++) {
        int src = g_srcs[e];
        const float* kp = &g_k[(size_t)src * DD];
        float p = 0.f;
#pragma unroll
        for (int r = 0; r < 8; r++) p = fmaf(qr[r], kp[r * 32 + lane], p);
#pragma unroll
        for (int off = 16; off; off >>= 1) p += __shfl_xor_sync(0xffffffffu, p, off);
        p *= 0.0625f;
        if (lane == 0) g_logits[e] = p;
        m = fmaxf(m, p);
    }

    float acc[8];
#pragma unroll
    for (int r = 0; r < 8; r++) acc[r] = 0.f;
    float ssum = 0.f;
    for (int e = beg; e < end; e++) {
        int src = g_srcs[e];
        float w = __expf(g_logits[e] - m);
        ssum += w;
        const float* vp = &g_v[(size_t)src * DD];
#pragma unroll
        for (int r = 0; r < 8; r++) acc[r] = fmaf(w, vp[r * 32 + lane], acc[r]);
    }

    float inv = (end > beg) ? (1.f / ssum) : 0.f;
#pragma unroll
    for (int r = 0; r < 8; r++) {
        float val = acc[r] * inv + g_s[(size_t)gw * DD + r * 32 + lane];
        val = fmaxf(val, 0.f);
        g_hA[(size_t)gw * DD + r * 32 + lane] = val;
        g_hrA[(size_t)gw * DD + r * 32 + lane] = rtf32(val);
    }
}

// -------- SAGE mean aggregation: warp per node; output tf32-rounded ----------
__global__ void mean_kernel(const float* __restrict__ h)
{
    int gw = (blockIdx.x * blockDim.x + threadIdx.x) >> 5;
    int lane = threadIdx.x & 31;
    if (gw >= NN) return;
    int beg = g_rowptr[gw], end = g_rowptr[gw + 1];

    float acc[8];
#pragma unroll
    for (int r = 0; r < 8; r++) acc[r] = 0.f;
    for (int e = beg; e < end; e++) {
        int src = g_srcs[e];
        const float* hp = &h[(size_t)src * DD];
#pragma unroll
        for (int r = 0; r < 8; r++) acc[r] += hp[r * 32 + lane];
    }
    int deg = end - beg;
    float inv = 1.f / (float)(deg > 0 ? deg : 1);
#pragma unroll
    for (int r = 0; r < 8; r++)
        g_mean[(size_t)gw * DD + r * 32 + lane] = rtf32(acc[r] * inv);
}

// -------- cached fork-join resources (host objects only; no device mem) ----
static cudaStream_t g_s2 = nullptr;
static cudaEvent_t  g_evF = nullptr, g_evJ = nullptr;
static cudaEvent_t  g_evA[3] = {nullptr, nullptr, nullptr};
static cudaEvent_t  g_evB[3] = {nullptr, nullptr, nullptr};

// -------- launch ----------
extern "C" void kernel_launch(void* const* d_in, const int* in_sizes, int n_in,
                              void* d_out, int out_size)
{
    const float* x     = (const float*)d_in[0];
    const int*   ei    = (const int*)d_in[1];       // int32 (jax x64 disabled)
    const float* Wq    = (const float*)d_in[2];
    const float* bq    = (const float*)d_in[3];
    const float* Wk    = (const float*)d_in[4];
    const float* bk    = (const float*)d_in[5];
    const float* Wv    = (const float*)d_in[6];
    const float* bv    = (const float*)d_in[7];
    const float* Ws    = (const float*)d_in[8];
    const float* bs    = (const float*)d_in[9];
    const float* Wl    = (const float*)d_in[10];
    const float* bl    = (const float*)d_in[11];
    const float* Wr    = (const float*)d_in[12];
    const float* gamma = (const float*)d_in[13];
    const float* beta  = (const float*)d_in[14];
    const float* alpha = (const float*)d_in[15];
    float*       out   = (float*)d_out;

    float *hA, *hB, *hrA, *hrB, *wr;
    void* cntp;
    cudaGetSymbolAddress((void**)&hA,  g_hA);
    cudaGetSymbolAddress((void**)&hB,  g_hB);
    cudaGetSymbolAddress((void**)&hrA, g_hrA);
    cudaGetSymbolAddress((void**)&hrB, g_hrB);
    cudaGetSymbolAddress((void**)&wr,  g_wr);
    cudaGetSymbolAddress(&cntp,        g_cnt);

    if (g_s2 == nullptr) {
        cudaStreamCreateWithFlags(&g_s2, cudaStreamNonBlocking);
        cudaEventCreateWithFlags(&g_evF, cudaEventDisableTiming);
        cudaEventCreateWithFlags(&g_evJ, cudaEventDisableTiming);
        for (int i = 0; i < 3; i++) {
            cudaEventCreateWithFlags(&g_evA[i], cudaEventDisableTiming);
            cudaEventCreateWithFlags(&g_evB[i], cudaEventDisableTiming);
        }
    }

    cudaFuncSetAttribute(gemm_qkvs, cudaFuncAttributeMaxDynamicSharedMemorySize, SMEM_BYTES);
    cudaFuncSetAttribute(gemm_r,    cudaFuncAttributeMaxDynamicSharedMemorySize, SMEM_BYTES);
    cudaFuncSetAttribute(gemm_l,    cudaFuncAttributeMaxDynamicSharedMemorySize, SMEM_BYTES);

    const int MT = (NN + 127) / 128;   // 79
    const int PREPV = NDTOT / 4 + 10 * (WSZ / 4);

    // ---- fork: CSR chain on g_s2, concurrent with prep + QKVS ----
    cudaEventRecord(g_evF, 0);
    cudaStreamWaitEvent(g_s2, g_evF, 0);

    cudaMemsetAsync(cntp, 0, NN * sizeof(int), g_s2);
    hist_kernel<<<(EE + 255) / 256, 256, 0, g_s2>>>(ei);
    scan_kernel<<<1, 1024, 0, g_s2>>>();
    scatter_kernel<<<(EE + 255) / 256, 256, 0, g_s2>>>(ei);

    // main stream: prep (float4) + fused projections
    round_prep<<<(PREPV + 255) / 256, 256>>>((const float4*)x,
                                             (const float4*)Wq, (const float4*)Wk,
                                             (const float4*)Wv, (const float4*)Ws,
                                             (const float4*)Wl, (const float4*)Wr);
    gemm_qkvs<<<dim3(MT, 8), 256, SMEM_BYTES>>>(bq, bk, bv, bs);

    // ---- join ----
    cudaEventRecord(g_evJ, g_s2);
    cudaStreamWaitEvent(0, g_evJ, 0);

    // TransformerConv
    attn_kernel<<<(NN * 32 + 255) / 256, 256>>>();

    // 3 SAGE layers: mean (stream2) overlaps gemm_r (stream0), then gemm_l
    float* hin  = hA;
    float* hrin = hrA;
    for (int l = 0; l < 3; l++) {
        cudaEventRecord(g_evA[l], 0);
        cudaStreamWaitEvent(g_s2, g_evA[l], 0);
        mean_kernel<<<(NN * 32 + 255) / 256, 256, 0, g_s2>>>(hin);
        cudaEventRecord(g_evB[l], g_s2);

        gemm_r<<<dim3(MT, 2), 256, SMEM_BYTES>>>(wr + (size_t)(7 + l) * WSZ, hrin);

        cudaStreamWaitEvent(0, g_evB[l], 0);

        float* hout  = (l == 2) ? out : ((l == 0) ? hB : hA);
        float* hrout = (l == 2) ? nullptr : ((hrin == hrA) ? hrB : hrA);
        gemm_l<<<dim3(MT, 2), 256, SMEM_BYTES>>>(wr + (size_t)(4 + l) * WSZ,
                                                 bl + (size_t)l * 256,
                                                 gamma + (size_t)l * 256, beta + (size_t)l * 256,
                                                 alpha, hin, hout, hrout);
        hin  = hout;
        hrin = hrout;
    }
}

// round 15
// speedup vs baseline: 1.1381x; 1.0889x over previous
#include <cuda_runtime.h>
#include <cstdint>

#define NN 10000
#define EE 320000
#define DD 256
#define NDTOT (NN*DD)
#define WSZ 65536

// -------- scratch (static device globals; no allocation) ----------
__device__ float g_q[NDTOT];
__device__ float g_k[NDTOT];
__device__ float g_v[NDTOT];
__device__ float g_s[NDTOT];
__device__ float g_hA[NDTOT];
__device__ float g_hB[NDTOT];
__device__ float g_hrA[NDTOT];        // tf32-rounded h, ping
__device__ float g_hrB[NDTOT];        // tf32-rounded h, pong
__device__ uint32_t g_hbf[NDTOT/2];   // bf16x2-packed h (mean-gather input)
__device__ float g_xr[NDTOT];         // tf32-rounded x
__device__ float g_wr[10*WSZ];        // rounded weights: Wq,Wk,Wv,Ws,Wl0..2,Wr0..2
__device__ float g_mean[NDTOT];       // tf32-rounded at production
__device__ float g_z[NDTOT];          // partial h@Wr accumulator
__device__ int   g_rowptr[NN + 1];
__device__ int   g_srcs[EE];
__device__ int   g_cnt[NN];
__device__ int   g_fill[NN];

// -------- helpers ----------
__device__ __forceinline__ float rtf32(float f)
{
    uint32_t u;
    asm("cvt.rna.tf32.f32 %0, %1;" : "=r"(u) : "f"(f));
    return __uint_as_float(u);
}

__device__ __forceinline__ uint32_t pack_bf16x2(float lo, float hi)
{
    uint32_t u;
    asm("cvt.rn.bf16x2.f32 %0, %1, %2;" : "=r"(u) : "f"(hi), "f"(lo));
    return u;
}

__device__ __forceinline__ void mma_tf32(float* c, const uint32_t* a, const uint32_t* b)
{
    asm volatile(
        "mma.sync.aligned.m16n8k8.row.col.f32.tf32.tf32.f32 "
        "{%0,%1,%2,%3}, {%4,%5,%6,%7}, {%8,%9}, {%0,%1,%2,%3};"
        : "+f"(c[0]), "+f"(c[1]), "+f"(c[2]), "+f"(c[3])
        : "r"(a[0]), "r"(a[1]), "r"(a[2]), "r"(a[3]), "r"(b[0]), "r"(b[1]));
}

__device__ __forceinline__ void cpasync16(uint32_t dst, const void* src, int szbytes)
{
    asm volatile("cp.async.ca.shared.global [%0], [%1], 16, %2;"
                 :: "r"(dst), "l"(src), "r"(szbytes));
}
__device__ __forceinline__ void cpasync_commit() { asm volatile("cp.async.commit_group;"); }
__device__ __forceinline__ void cpasync_wait1()  { asm volatile("cp.async.wait_group 1;"); }
__device__ __forceinline__ void cpasync_wait0()  { asm volatile("cp.async.wait_group 0;"); }

// -------- prep: tf32-round x and all weights into scratch (float4) --------
__global__ void round_prep(const float4* __restrict__ x,
                           const float4* __restrict__ Wq, const float4* __restrict__ Wk,
                           const float4* __restrict__ Wv, const float4* __restrict__ Ws,
                           const float4* __restrict__ Wl, const float4* __restrict__ Wr)
{
    int i = blockIdx.x * blockDim.x + threadIdx.x;
    const int XV = NDTOT / 4;           // 640000
    const int WV = WSZ / 4;             // 16384
    const int totalv = XV + 10 * WV;
    if (i >= totalv) return;
    float4 v;
    float4* dst;
    if (i < XV) {
        v = x[i];
        dst = reinterpret_cast<float4*>(g_xr) + i;
    } else {
        int j = i - XV;
        int m = j >> 14, o = j & (WV - 1);
        const float4* src;
        if      (m == 0) src = Wq;
        else if (m == 1) src = Wk;
        else if (m == 2) src = Wv;
        else if (m == 3) src = Ws;
        else if (m <  7) src = Wl + (size_t)(m - 4) * WV;
        else             src = Wr + (size_t)(m - 7) * WV;
        v = src[o];
        dst = reinterpret_cast<float4*>(g_wr) + j;
    }
    v.x = rtf32(v.x); v.y = rtf32(v.y); v.z = rtf32(v.z); v.w = rtf32(v.w);
    *dst = v;
}

#define APAD 36
#define BPAD 136
#define ASZ (128*APAD)
#define BSZ (32*BPAD)
#define SMEM_BYTES ((2*ASZ + 2*BSZ) * 4)   // 71680

// ---- issue one chunk (A 128x32 from Asrc at col kt, B 32x128 from Bsrc) ----
#define ISSUE_CHUNK(Asrc, Bsrc, kt, buf)                                        \
    {                                                                           \
        uint32_t abase = sbase + (uint32_t)((buf) * ASZ) * 4u;                  \
        uint32_t bbase = sbase + (uint32_t)(2 * ASZ + (buf) * BSZ) * 4u;        \
        _Pragma("unroll")                                                       \
        for (int i = 0; i < 4; i++) {                                           \
            int idx = i * 256 + tid;                                            \
            int ar = idx >> 3, acq = (idx & 7) * 4;                             \
            int grow = bm + ar;                                                 \
            int sz = (grow < NN) ? 16 : 0;                                      \
            cpasync16(abase + (uint32_t)(ar * APAD + acq) * 4u,                 \
                      (Asrc) + (size_t)grow * DD + (kt) + acq, sz);             \
        }                                                                       \
        _Pragma("unroll")                                                       \
        for (int i = 0; i < 4; i++) {                                           \
            int idx = i * 256 + tid;                                            \
            int br = idx >> 5, bcq = (idx & 31) * 4;                            \
            cpasync16(bbase + (uint32_t)(br * BPAD + bcq) * 4u,                 \
                      (Bsrc) + (size_t)((kt) + br) * DD + bn + bcq, 16);        \
        }                                                                       \
        cpasync_commit();                                                       \
    }

#define COMPUTE_CHUNK(buf)                                                      \
    {                                                                           \
        const float* pA = s_dyn + (buf) * ASZ;                                  \
        const float* pB = s_dyn + 2 * ASZ + (buf) * BSZ;                        \
        _Pragma("unroll")                                                       \
        for (int k8 = 0; k8 < 4; k8++) {                                        \
            const int kb = k8 * 8;                                              \
            uint32_t af[4][4], bf[4][2];                                        \
            _Pragma("unroll")                                                   \
            for (int mt = 0; mt < 4; mt++) {                                    \
                int mr = wm + mt * 16 + fr;                                     \
                af[mt][0] = __float_as_uint(pA[mr * APAD + kb + fc]);           \
                af[mt][1] = __float_as_uint(pA[(mr + 8) * APAD + kb + fc]);     \
                af[mt][2] = __float_as_uint(pA[mr * APAD + kb + fc + 4]);       \
                af[mt][3] = __float_as_uint(pA[(mr + 8) * APAD + kb + fc + 4]); \
            }                                                                   \
            _Pragma("unroll")                                                   \
            for (int nt = 0; nt < 4; nt++) {                                    \
                int nc = wn + nt * 8 + fr;                                      \
                bf[nt][0] = __float_as_uint(pB[(kb + fc) * BPAD + nc]);         \
                bf[nt][1] = __float_as_uint(pB[(kb + fc + 4) * BPAD + nc]);     \
            }                                                                   \
            _Pragma("unroll")                                                   \
            for (int mt = 0; mt < 4; mt++)                                      \
                _Pragma("unroll")                                               \
                for (int nt = 0; nt < 4; nt++)                                  \
                    mma_tf32(acc[mt][nt], af[mt], bf[nt]);                      \
        }                                                                       \
    }

#define GEMM_PROLOGUE()                                                         \
    extern __shared__ float s_dyn[];                                            \
    const uint32_t sbase = (uint32_t)__cvta_generic_to_shared(s_dyn);           \
    const int tid  = threadIdx.x;                                               \
    const int lane = tid & 31;                                                  \
    const int warp = tid >> 5;                                                  \
    const int wm = (warp >> 2) * 64;                                            \
    const int wn = (warp & 3) * 32;                                             \
    const int fr = lane >> 2;                                                   \
    const int fc = lane & 3;                                                    \
    const int bm = blockIdx.x * 128;                                            \
    float acc[4][4][4];                                                         \
    _Pragma("unroll")                                                           \
    for (int mt = 0; mt < 4; mt++)                                              \
        _Pragma("unroll")                                                       \
        for (int nt = 0; nt < 4; nt++)                                          \
            _Pragma("unroll")                                                   \
            for (int r = 0; r < 4; r++) acc[mt][nt][r] = 0.f;

#define GEMM_MAINLOOP(Asrc, Bsrc)                                               \
    {                                                                           \
        const int NC = 8;                                                       \
        ISSUE_CHUNK(Asrc, Bsrc, 0, 0);                                          \
        ISSUE_CHUNK(Asrc, Bsrc, 32, 1);                                         \
        for (int c = 0; c < NC; c++) {                                          \
            if (c + 1 < NC) cpasync_wait1(); else cpasync_wait0();              \
            __syncthreads();                                                    \
            COMPUTE_CHUNK(c & 1);                                               \
            __syncthreads();                                                    \
            if (c + 2 < NC) ISSUE_CHUNK(Asrc, Bsrc, (c + 2) * 32, c & 1);       \
        }                                                                       \
    }

// =====================================================================
// Fused QKVS projection: A = g_xr (pre-rounded), B = g_wr[mat]
// grid (79, 8): blockIdx.y>>1 selects matrix, &1 selects N-half.
// =====================================================================
__global__ void __launch_bounds__(256, 2)
gemm_qkvs(const float* __restrict__ bq, const float* __restrict__ bk,
          const float* __restrict__ bv, const float* __restrict__ bs)
{
    GEMM_PROLOGUE();
    const int mat = blockIdx.y >> 1;
    const int bn  = (blockIdx.y & 1) * 128;

    const float* B = g_wr + (size_t)mat * WSZ;
    const float* bias; float* C;
    if      (mat == 0) { bias = bq; C = g_q; }
    else if (mat == 1) { bias = bk; C = g_k; }
    else if (mat == 2) { bias = bv; C = g_v; }
    else               { bias = bs; C = g_s; }

    GEMM_MAINLOOP(g_xr, B);

    float bb[4][2];
#pragma unroll
    for (int nt = 0; nt < 4; nt++) {
        int col = bn + wn + nt * 8 + fc * 2;
        bb[nt][0] = bias[col]; bb[nt][1] = bias[col + 1];
    }
#pragma unroll
    for (int mt = 0; mt < 4; mt++) {
#pragma unroll
        for (int nt = 0; nt < 4; nt++) {
            int row = bm + wm + mt * 16 + fr;
            int col = bn + wn + nt * 8 + fc * 2;
            if (row < NN) {
                float2 o = make_float2(acc[mt][nt][0] + bb[nt][0], acc[mt][nt][1] + bb[nt][1]);
                *reinterpret_cast<float2*>(&C[(size_t)row * DD + col]) = o;
            }
            if (row + 8 < NN) {
                float2 o = make_float2(acc[mt][nt][2] + bb[nt][0], acc[mt][nt][3] + bb[nt][1]);
                *reinterpret_cast<float2*>(&C[(size_t)(row + 8) * DD + col]) = o;
            }
        }
    }
}

// =====================================================================
// SAGE half 1: g_z = hr_in @ Wr   (no epilogue; runs concurrent w/ mean)
// =====================================================================
__global__ void __launch_bounds__(256, 2)
gemm_r(const float* __restrict__ Br, const float* __restrict__ hr_in)
{
    GEMM_PROLOGUE();
    const int bn = blockIdx.y * 128;

    GEMM_MAINLOOP(hr_in, Br);

#pragma unroll
    for (int mt = 0; mt < 4; mt++) {
#pragma unroll
        for (int nt = 0; nt < 4; nt++) {
            int row = bm + wm + mt * 16 + fr;
            int col = bn + wn + nt * 8 + fc * 2;
            if (row < NN)
                *reinterpret_cast<float2*>(&g_z[(size_t)row * DD + col]) =
                    make_float2(acc[mt][nt][0], acc[mt][nt][1]);
            if (row + 8 < NN)
                *reinterpret_cast<float2*>(&g_z[(size_t)(row + 8) * DD + col]) =
                    make_float2(acc[mt][nt][2], acc[mt][nt][3]);
        }
    }
}

// =====================================================================
// SAGE half 2: acc = g_mean @ Wl; epilogue adds g_z + bl, BN + gated
// residual (full-precision hin) + relu -> hout (+ rounded hr_out + bf16)
// =====================================================================
__global__ void __launch_bounds__(256, 2)
gemm_l(const float* __restrict__ Bl, const float* __restrict__ bl,
       const float* __restrict__ gamma, const float* __restrict__ beta,
       const float* __restrict__ alpha,
       const float* __restrict__ hin,
       float* __restrict__ hout, float* __restrict__ hr_out)
{
    GEMM_PROLOGUE();
    const int bn = blockIdx.y * 128;

    GEMM_MAINLOOP(g_mean, Bl);

    const float al  = 1.f / (1.f + __expf(-alpha[0]));
    const float oma = 1.f - al;
    const float BNS = 0.9999950000374994f;   // 1/sqrt(1+1e-5)

    float blv[4][2], gv[4][2], bev[4][2];
#pragma unroll
    for (int nt = 0; nt < 4; nt++) {
        int col = bn + wn + nt * 8 + fc * 2;
        blv[nt][0] = bl[col];    blv[nt][1] = bl[col + 1];
        gv[nt][0]  = gamma[col]; gv[nt][1]  = gamma[col + 1];
        bev[nt][0] = beta[col];  bev[nt][1] = beta[col + 1];
    }

#pragma unroll
    for (int mt = 0; mt < 4; mt++) {
#pragma unroll
        for (int nt = 0; nt < 4; nt++) {
            int row = bm + wm + mt * 16 + fr;
            int col = bn + wn + nt * 8 + fc * 2;
#pragma unroll
            for (int h = 0; h < 2; h++) {
                int rr = row + h * 8;
                if (rr < NN) {
                    float2 zr = *reinterpret_cast<const float2*>(&g_z[(size_t)rr * DD + col]);
                    float2 rv = *reinterpret_cast<const float2*>(&hin[(size_t)rr * DD + col]);
                    float z0 = fmaf((acc[mt][nt][h*2]   + zr.x + blv[nt][0]) * BNS, gv[nt][0], bev[nt][0]);
                    float z1 = fmaf((acc[mt][nt][h*2+1] + zr.y + blv[nt][1]) * BNS, gv[nt][1], bev[nt][1]);
                    float o0 = fmaxf(fmaf(al, z0, oma * rv.x), 0.f);
                    float o1 = fmaxf(fmaf(al, z1, oma * rv.y), 0.f);
                    *reinterpret_cast<float2*>(&hout[(size_t)rr * DD + col]) = make_float2(o0, o1);
                    if (hr_out) {
                        *reinterpret_cast<float2*>(&hr_out[(size_t)rr * DD + col]) =
                            make_float2(rtf32(o0), rtf32(o1));
                        g_hbf[(size_t)rr * 128 + (col >> 1)] = pack_bf16x2(o0, o1);
                    }
                }
            }
        }
    }
}

// -------- CSR build ----------
__global__ void hist_kernel(const int* __restrict__ ei)
{
    int e = blockIdx.x * blockDim.x + threadIdx.x;
    if (e >= EE) return;
    atomicAdd(&g_cnt[ei[EE + e]], 1);
}

// coalesced smem-staged block scan: 1024 threads x 10 elems
__global__ void scan_kernel()
{
    __shared__ int sh[10240];          // 40 KB
    __shared__ int wsum[32];
    const int tid = threadIdx.x;
    const int lane = tid & 31, wid = tid >> 5;
    const int PER = 10;

    for (int i = tid; i < 10240; i += 1024)
        sh[i] = (i < NN) ? g_cnt[i] : 0;
    __syncthreads();

    int base = tid * PER;
    int loc[PER];
    int s = 0;
#pragma unroll
    for (int j = 0; j < PER; j++) {
        s += sh[base + j];
        loc[j] = s;
    }
    int ssum = s;
#pragma unroll
    for (int off = 1; off < 32; off <<= 1) {
        int t = __shfl_up_sync(0xffffffffu, ssum, off);
        if (lane >= off) ssum += t;
    }
    if (lane == 31) wsum[wid] = ssum;
    __syncthreads();
    if (wid == 0) {
        int w = wsum[lane];
#pragma unroll
        for (int off = 1; off < 32; off <<= 1) {
            int t = __shfl_up_sync(0xffffffffu, w, off);
            if (lane >= off) w += t;
        }
        wsum[lane] = w;
    }
    __syncthreads();

    int offset = ssum - s + (wid > 0 ? wsum[wid - 1] : 0);
#pragma unroll
    for (int j = 0; j < PER; j++)
        sh[base + j] = offset + loc[j];
    __syncthreads();

    if (tid == 0) { g_rowptr[0] = 0; g_fill[0] = 0; }
    for (int i = tid; i < NN; i += 1024) {
        int incl = sh[i];
        g_rowptr[i + 1] = incl;
        if (i > 0) g_fill[i] = sh[i - 1];
    }
}

__global__ void scatter_kernel(const int* __restrict__ ei)
{
    int e = blockIdx.x * blockDim.x + threadIdx.x;
    if (e >= EE) return;
    int src = ei[e];
    int dst = ei[EE + e];
    int pos = atomicAdd(&g_fill[dst], 1);
    g_srcs[pos] = src;
}

// -------- TransformerConv: warp per node, SINGLE-pass softmax (no max;
// logits ~ N(0,1), exp range safe in fp32) reading k+v in one edge loop ----
__global__ void attn_kernel()
{
    int gw = (blockIdx.x * blockDim.x + threadIdx.x) >> 5;
    int lane = threadIdx.x & 31;
    if (gw >= NN) return;
    int beg = g_rowptr[gw], end = g_rowptr[gw + 1];

    float2 qr[4];
#pragma unroll
    for (int r = 0; r < 4; r++)
        qr[r] = *reinterpret_cast<const float2*>(&g_q[(size_t)gw * DD + (r * 32 + lane) * 2]);

    float2 acc[4];
#pragma unroll
    for (int r = 0; r < 4; r++) acc[r] = make_float2(0.f, 0.f);
    float ssum = 0.f;

    for (int e = beg; e < end; e++) {
        int src = g_srcs[e];
        const float* kp = &g_k[(size_t)src * DD];
        const float* vp = &g_v[(size_t)src * DD];
        float p = 0.f;
#pragma unroll
        for (int r = 0; r < 4; r++) {
            float2 kv = *reinterpret_cast<const float2*>(&kp[(r * 32 + lane) * 2]);
            p = fmaf(qr[r].x, kv.x, p);
            p = fmaf(qr[r].y, kv.y, p);
        }
#pragma unroll
        for (int off = 16; off; off >>= 1) p += __shfl_xor_sync(0xffffffffu, p, off);
        float w = __expf(p * 0.0625f);     // / sqrt(256)
        ssum += w;
#pragma unroll
        for (int r = 0; r < 4; r++) {
            float2 vv = *reinterpret_cast<const float2*>(&vp[(r * 32 + lane) * 2]);
            acc[r].x = fmaf(w, vv.x, acc[r].x);
            acc[r].y = fmaf(w, vv.y, acc[r].y);
        }
    }

    float inv = (end > beg) ? (1.f / ssum) : 0.f;
#pragma unroll
    for (int r = 0; r < 4; r++) {
        int p2 = r * 32 + lane;
        float2 sv = *reinterpret_cast<const float2*>(&g_s[(size_t)gw * DD + p2 * 2]);
        float o0 = fmaxf(acc[r].x * inv + sv.x, 0.f);
        float o1 = fmaxf(acc[r].y * inv + sv.y, 0.f);
        *reinterpret_cast<float2*>(&g_hA[(size_t)gw * DD + p2 * 2])  = make_float2(o0, o1);
        *reinterpret_cast<float2*>(&g_hrA[(size_t)gw * DD + p2 * 2]) = make_float2(rtf32(o0), rtf32(o1));
        g_hbf[(size_t)gw * 128 + p2] = pack_bf16x2(o0, o1);
    }
}

// -------- SAGE mean: warp per node, bf16x2 gather (half bytes) ----------
__global__ void mean_kernel()
{
    int gw = (blockIdx.x * blockDim.x + threadIdx.x) >> 5;
    int lane = threadIdx.x & 31;
    if (gw >= NN) return;
    int beg = g_rowptr[gw], end = g_rowptr[gw + 1];

    float2 acc[4];
#pragma unroll
    for (int r = 0; r < 4; r++) acc[r] = make_float2(0.f, 0.f);
    for (int e = beg; e < end; e++) {
        int src = g_srcs[e];
        const uint32_t* hp = &g_hbf[(size_t)src * 128];
#pragma unroll
        for (int r = 0; r < 4; r++) {
            uint32_t u = hp[r * 32 + lane];
            acc[r].x += __uint_as_float(u << 16);          // lo bf16 -> fp32
            acc[r].y += __uint_as_float(u & 0xffff0000u);  // hi bf16 -> fp32
        }
    }
    int deg = end - beg;
    float invd = 1.f / (float)(deg > 0 ? deg : 1);
#pragma unroll
    for (int r = 0; r < 4; r++) {
        int p2 = r * 32 + lane;
        *reinterpret_cast<float2*>(&g_mean[(size_t)gw * DD + p2 * 2]) =
            make_float2(rtf32(acc[r].x * invd), rtf32(acc[r].y * invd));
    }
}

// -------- cached fork-join resources (host objects only; no device mem) ----
static cudaStream_t g_s2 = nullptr;
static cudaEvent_t  g_evF = nullptr, g_evJ = nullptr;
static cudaEvent_t  g_evA[3] = {nullptr, nullptr, nullptr};
static cudaEvent_t  g_evB[3] = {nullptr, nullptr, nullptr};

// -------- launch ----------
extern "C" void kernel_launch(void* const* d_in, const int* in_sizes, int n_in,
                              void* d_out, int out_size)
{
    const float* x     = (const float*)d_in[0];
    const int*   ei    = (const int*)d_in[1];       // int32 (jax x64 disabled)
    const float* Wq    = (const float*)d_in[2];
    const float* bq    = (const float*)d_in[3];
    const float* Wk    = (const float*)d_in[4];
    const float* bk    = (const float*)d_in[5];
    const float* Wv    = (const float*)d_in[6];
    const float* bv    = (const float*)d_in[7];
    const float* Ws    = (const float*)d_in[8];
    const float* bs    = (const float*)d_in[9];
    const float* Wl    = (const float*)d_in[10];
    const float* bl    = (const float*)d_in[11];
    const float* Wr    = (const float*)d_in[12];
    const float* gamma = (const float*)d_in[13];
    const float* beta  = (const float*)d_in[14];
    const float* alpha = (const float*)d_in[15];
    float*       out   = (float*)d_out;

    float *hA, *hB, *hrA, *hrB, *wr;
    void* cntp;
    cudaGetSymbolAddress((void**)&hA,  g_hA);
    cudaGetSymbolAddress((void**)&hB,  g_hB);
    cudaGetSymbolAddress((void**)&hrA, g_hrA);
    cudaGetSymbolAddress((void**)&hrB, g_hrB);
    cudaGetSymbolAddress((void**)&wr,  g_wr);
    cudaGetSymbolAddress(&cntp,        g_cnt);

    if (g_s2 == nullptr) {
        cudaStreamCreateWithFlags(&g_s2, cudaStreamNonBlocking);
        cudaEventCreateWithFlags(&g_evF, cudaEventDisableTiming);
        cudaEventCreateWithFlags(&g_evJ, cudaEventDisableTiming);
        for (int i = 0; i < 3; i++) {
            cudaEventCreateWithFlags(&g_evA[i], cudaEventDisableTiming);
            cudaEventCreateWithFlags(&g_evB[i], cudaEventDisableTiming);
        }
    }

    cudaFuncSetAttribute(gemm_qkvs, cudaFuncAttributeMaxDynamicSharedMemorySize, SMEM_BYTES);
    cudaFuncSetAttribute(gemm_r,    cudaFuncAttributeMaxDynamicSharedMemorySize, SMEM_BYTES);
    cudaFuncSetAttribute(gemm_l,    cudaFuncAttributeMaxDynamicSharedMemorySize, SMEM_BYTES);

    const int MT = (NN + 127) / 128;   // 79
    const int PREPV = NDTOT / 4 + 10 * (WSZ / 4);

    // ---- fork: CSR chain on g_s2, concurrent with prep + QKVS ----
    cudaEventRecord(g_evF, 0);
    cudaStreamWaitEvent(g_s2, g_evF, 0);

    cudaMemsetAsync(cntp, 0, NN * sizeof(int), g_s2);
    hist_kernel<<<(EE + 255) / 256, 256, 0, g_s2>>>(ei);
    scan_kernel<<<1, 1024, 0, g_s2>>>();
    scatter_kernel<<<(EE + 255) / 256, 256, 0, g_s2>>>(ei);

    // main stream: prep (float4) + fused projections
    round_prep<<<(PREPV + 255) / 256, 256>>>((const float4*)x,
                                             (const float4*)Wq, (const float4*)Wk,
                                             (const float4*)Wv, (const float4*)Ws,
                                             (const float4*)Wl, (const float4*)Wr);
    gemm_qkvs<<<dim3(MT, 8), 256, SMEM_BYTES>>>(bq, bk, bv, bs);

    // ---- join ----
    cudaEventRecord(g_evJ, g_s2);
    cudaStreamWaitEvent(0, g_evJ, 0);

    // TransformerConv (single pass)
    attn_kernel<<<(NN * 32 + 255) / 256, 256>>>();

    // 3 SAGE layers: mean (stream2, bf16 gather) overlaps gemm_r, then gemm_l
    float* hin  = hA;
    float* hrin = hrA;
    for (int l = 0; l < 3; l++) {
        cudaEventRecord(g_evA[l], 0);
        cudaStreamWaitEvent(g_s2, g_evA[l], 0);
        mean_kernel<<<(NN * 32 + 255) / 256, 256, 0, g_s2>>>();
        cudaEventRecord(g_evB[l], g_s2);

        gemm_r<<<dim3(MT, 2), 256, SMEM_BYTES>>>(wr + (size_t)(7 + l) * WSZ, hrin);

        cudaStreamWaitEvent(0, g_evB[l], 0);

        float* hout  = (l == 2) ? out : ((l == 0) ? hB : hA);
        float* hrout = (l == 2) ? nullptr : ((hrin == hrA) ? hrB : hrA);
        gemm_l<<<dim3(MT, 2), 256, SMEM_BYTES>>>(wr + (size_t)(4 + l) * WSZ,
                                                 bl + (size_t)l * 256,
                                                 gamma + (size_t)l * 256, beta + (size_t)l * 256,
                                                 alpha, hin, hout, hrout);
        hin  = hout;
        hrin = hrout;
    }
}

// round 16
// speedup vs baseline: 1.1458x; 1.0067x over previous
#include <cuda_runtime.h>
#include <cstdint>

#define NN 10000
#define EE 320000
#define DD 256
#define NDTOT (NN*DD)
#define WSZ 65536

// -------- scratch (static device globals; no allocation) ----------
__device__ float g_q[NDTOT];
__device__ float g_k[NDTOT];
__device__ float g_v[NDTOT];
__device__ float g_s[NDTOT];
__device__ float g_hA[NDTOT];
__device__ float g_hB[NDTOT];
__device__ float g_hrA[NDTOT];        // tf32-rounded h, ping
__device__ float g_hrB[NDTOT];        // tf32-rounded h, pong
__device__ uint32_t g_hbf[NDTOT/2];   // bf16x2-packed h (mean-gather input)
__device__ uint32_t g_kbf[NDTOT/2];   // bf16x2-packed k (attn gather input)
__device__ uint32_t g_vbf[NDTOT/2];   // bf16x2-packed v (attn gather input)
__device__ float g_xr[NDTOT];         // tf32-rounded x
__device__ float g_wr[10*WSZ];        // rounded weights: Wq,Wk,Wv,Ws,Wl0..2,Wr0..2
__device__ float g_mean[NDTOT];       // tf32-rounded at production
__device__ float g_z[NDTOT];          // partial h@Wr accumulator
__device__ int   g_rowptr[NN + 1];
__device__ int   g_srcs[EE];
__device__ int   g_cnt[NN];
__device__ int   g_fill[NN];

// -------- helpers ----------
__device__ __forceinline__ float rtf32(float f)
{
    uint32_t u;
    asm("cvt.rna.tf32.f32 %0, %1;" : "=r"(u) : "f"(f));
    return __uint_as_float(u);
}

__device__ __forceinline__ uint32_t pack_bf16x2(float lo, float hi)
{
    uint32_t u;
    asm("cvt.rn.bf16x2.f32 %0, %1, %2;" : "=r"(u) : "f"(hi), "f"(lo));
    return u;
}

__device__ __forceinline__ void mma_tf32(float* c, const uint32_t* a, const uint32_t* b)
{
    asm volatile(
        "mma.sync.aligned.m16n8k8.row.col.f32.tf32.tf32.f32 "
        "{%0,%1,%2,%3}, {%4,%5,%6,%7}, {%8,%9}, {%0,%1,%2,%3};"
        : "+f"(c[0]), "+f"(c[1]), "+f"(c[2]), "+f"(c[3])
        : "r"(a[0]), "r"(a[1]), "r"(a[2]), "r"(a[3]), "r"(b[0]), "r"(b[1]));
}

__device__ __forceinline__ void cpasync16(uint32_t dst, const void* src, int szbytes)
{
    asm volatile("cp.async.ca.shared.global [%0], [%1], 16, %2;"
                 :: "r"(dst), "l"(src), "r"(szbytes));
}
__device__ __forceinline__ void cpasync_commit() { asm volatile("cp.async.commit_group;"); }
__device__ __forceinline__ void cpasync_wait1()  { asm volatile("cp.async.wait_group 1;"); }
__device__ __forceinline__ void cpasync_wait0()  { asm volatile("cp.async.wait_group 0;"); }

// -------- prep: tf32-round x and all weights into scratch (float4) --------
__global__ void round_prep(const float4* __restrict__ x,
                           const float4* __restrict__ Wq, const float4* __restrict__ Wk,
                           const float4* __restrict__ Wv, const float4* __restrict__ Ws,
                           const float4* __restrict__ Wl, const float4* __restrict__ Wr)
{
    int i = blockIdx.x * blockDim.x + threadIdx.x;
    const int XV = NDTOT / 4;           // 640000
    const int WV = WSZ / 4;             // 16384
    const int totalv = XV + 10 * WV;
    if (i >= totalv) return;
    float4 v;
    float4* dst;
    if (i < XV) {
        v = x[i];
        dst = reinterpret_cast<float4*>(g_xr) + i;
    } else {
        int j = i - XV;
        int m = j >> 14, o = j & (WV - 1);
        const float4* src;
        if      (m == 0) src = Wq;
        else if (m == 1) src = Wk;
        else if (m == 2) src = Wv;
        else if (m == 3) src = Ws;
        else if (m <  7) src = Wl + (size_t)(m - 4) * WV;
        else             src = Wr + (size_t)(m - 7) * WV;
        v = src[o];
        dst = reinterpret_cast<float4*>(g_wr) + j;
    }
    v.x = rtf32(v.x); v.y = rtf32(v.y); v.z = rtf32(v.z); v.w = rtf32(v.w);
    *dst = v;
}

#define APAD 36
#define BPAD 136
#define ASZ (128*APAD)
#define BSZ (32*BPAD)
#define SMEM_BYTES ((2*ASZ + 2*BSZ) * 4)   // 71680

// ---- issue one chunk (A 128x32 from Asrc at col kt, B 32x128 from Bsrc) ----
#define ISSUE_CHUNK(Asrc, Bsrc, kt, buf)                                        \
    {                                                                           \
        uint32_t abase = sbase + (uint32_t)((buf) * ASZ) * 4u;                  \
        uint32_t bbase = sbase + (uint32_t)(2 * ASZ + (buf) * BSZ) * 4u;        \
        _Pragma("unroll")                                                       \
        for (int i = 0; i < 4; i++) {                                           \
            int idx = i * 256 + tid;                                            \
            int ar = idx >> 3, acq = (idx & 7) * 4;                             \
            int grow = bm + ar;                                                 \
            int sz = (grow < NN) ? 16 : 0;                                      \
            cpasync16(abase + (uint32_t)(ar * APAD + acq) * 4u,                 \
                      (Asrc) + (size_t)grow * DD + (kt) + acq, sz);             \
        }                                                                       \
        _Pragma("unroll")                                                       \
        for (int i = 0; i < 4; i++) {                                           \
            int idx = i * 256 + tid;                                            \
            int br = idx >> 5, bcq = (idx & 31) * 4;                            \
            cpasync16(bbase + (uint32_t)(br * BPAD + bcq) * 4u,                 \
                      (Bsrc) + (size_t)((kt) + br) * DD + bn + bcq, 16);        \
        }                                                                       \
        cpasync_commit();                                                       \
    }

#define COMPUTE_CHUNK(buf)                                                      \
    {                                                                           \
        const float* pA = s_dyn + (buf) * ASZ;                                  \
        const float* pB = s_dyn + 2 * ASZ + (buf) * BSZ;                        \
        _Pragma("unroll")                                                       \
        for (int k8 = 0; k8 < 4; k8++) {                                        \
            const int kb = k8 * 8;                                              \
            uint32_t af[4][4], bf[4][2];                                        \
            _Pragma("unroll")                                                   \
            for (int mt = 0; mt < 4; mt++) {                                    \
                int mr = wm + mt * 16 + fr;                                     \
                af[mt][0] = __float_as_uint(pA[mr * APAD + kb + fc]);           \
                af[mt][1] = __float_as_uint(pA[(mr + 8) * APAD + kb + fc]);     \
                af[mt][2] = __float_as_uint(pA[mr * APAD + kb + fc + 4]);       \
                af[mt][3] = __float_as_uint(pA[(mr + 8) * APAD + kb + fc + 4]); \
            }                                                                   \
            _Pragma("unroll")                                                   \
            for (int nt = 0; nt < 4; nt++) {                                    \
                int nc = wn + nt * 8 + fr;                                      \
                bf[nt][0] = __float_as_uint(pB[(kb + fc) * BPAD + nc]);         \
                bf[nt][1] = __float_as_uint(pB[(kb + fc + 4) * BPAD + nc]);     \
            }                                                                   \
            _Pragma("unroll")                                                   \
            for (int mt = 0; mt < 4; mt++)                                      \
                _Pragma("unroll")                                               \
                for (int nt = 0; nt < 4; nt++)                                  \
                    mma_tf32(acc[mt][nt], af[mt], bf[nt]);                      \
        }                                                                       \
    }

#define GEMM_PROLOGUE()                                                         \
    extern __shared__ float s_dyn[];                                            \
    const uint32_t sbase = (uint32_t)__cvta_generic_to_shared(s_dyn);           \
    const int tid  = threadIdx.x;                                               \
    const int lane = tid & 31;                                                  \
    const int warp = tid >> 5;                                                  \
    const int wm = (warp >> 2) * 64;                                            \
    const int wn = (warp & 3) * 32;                                             \
    const int fr = lane >> 2;                                                   \
    const int fc = lane & 3;                                                    \
    const int bm = blockIdx.x * 128;                                            \
    float acc[4][4][4];                                                         \
    _Pragma("unroll")                                                           \
    for (int mt = 0; mt < 4; mt++)                                              \
        _Pragma("unroll")                                                       \
        for (int nt = 0; nt < 4; nt++)                                          \
            _Pragma("unroll")                                                   \
            for (int r = 0; r < 4; r++) acc[mt][nt][r] = 0.f;

#define GEMM_MAINLOOP(Asrc, Bsrc)                                               \
    {                                                                           \
        const int NC = 8;                                                       \
        ISSUE_CHUNK(Asrc, Bsrc, 0, 0);                                          \
        ISSUE_CHUNK(Asrc, Bsrc, 32, 1);                                         \
        for (int c = 0; c < NC; c++) {                                          \
            if (c + 1 < NC) cpasync_wait1(); else cpasync_wait0();              \
            __syncthreads();                                                    \
            COMPUTE_CHUNK(c & 1);                                               \
            __syncthreads();                                                    \
            if (c + 2 < NC) ISSUE_CHUNK(Asrc, Bsrc, (c + 2) * 32, c & 1);       \
        }                                                                       \
    }

// =====================================================================
// Fused QKVS projection: A = g_xr (pre-rounded), B = g_wr[mat]
// grid (79, 8). k and v also stored as packed bf16x2 for the attn gather.
// =====================================================================
__global__ void __launch_bounds__(256, 2)
gemm_qkvs(const float* __restrict__ bq, const float* __restrict__ bk,
          const float* __restrict__ bv, const float* __restrict__ bs)
{
    GEMM_PROLOGUE();
    const int mat = blockIdx.y >> 1;
    const int bn  = (blockIdx.y & 1) * 128;

    const float* B = g_wr + (size_t)mat * WSZ;
    const float* bias; float* C;
    if      (mat == 0) { bias = bq; C = g_q; }
    else if (mat == 1) { bias = bk; C = g_k; }
    else if (mat == 2) { bias = bv; C = g_v; }
    else               { bias = bs; C = g_s; }

    uint32_t* BF = (mat == 1) ? g_kbf : ((mat == 2) ? g_vbf : nullptr);

    GEMM_MAINLOOP(g_xr, B);

    float bb[4][2];
#pragma unroll
    for (int nt = 0; nt < 4; nt++) {
        int col = bn + wn + nt * 8 + fc * 2;
        bb[nt][0] = bias[col]; bb[nt][1] = bias[col + 1];
    }
#pragma unroll
    for (int mt = 0; mt < 4; mt++) {
#pragma unroll
        for (int nt = 0; nt < 4; nt++) {
            int row = bm + wm + mt * 16 + fr;
            int col = bn + wn + nt * 8 + fc * 2;
            if (row < NN) {
                float2 o = make_float2(acc[mt][nt][0] + bb[nt][0], acc[mt][nt][1] + bb[nt][1]);
                *reinterpret_cast<float2*>(&C[(size_t)row * DD + col]) = o;
                if (BF) BF[(size_t)row * 128 + (col >> 1)] = pack_bf16x2(o.x, o.y);
            }
            if (row + 8 < NN) {
                float2 o = make_float2(acc[mt][nt][2] + bb[nt][0], acc[mt][nt][3] + bb[nt][1]);
                *reinterpret_cast<float2*>(&C[(size_t)(row + 8) * DD + col]) = o;
                if (BF) BF[(size_t)(row + 8) * 128 + (col >> 1)] = pack_bf16x2(o.x, o.y);
            }
        }
    }
}

// =====================================================================
// SAGE half 1: g_z = hr_in @ Wr   (no epilogue; runs concurrent w/ mean)
// =====================================================================
__global__ void __launch_bounds__(256, 2)
gemm_r(const float* __restrict__ Br, const float* __restrict__ hr_in)
{
    GEMM_PROLOGUE();
    const int bn = blockIdx.y * 128;

    GEMM_MAINLOOP(hr_in, Br);

#pragma unroll
    for (int mt = 0; mt < 4; mt++) {
#pragma unroll
        for (int nt = 0; nt < 4; nt++) {
            int row = bm + wm + mt * 16 + fr;
            int col = bn + wn + nt * 8 + fc * 2;
            if (row < NN)
                *reinterpret_cast<float2*>(&g_z[(size_t)row * DD + col]) =
                    make_float2(acc[mt][nt][0], acc[mt][nt][1]);
            if (row + 8 < NN)
                *reinterpret_cast<float2*>(&g_z[(size_t)(row + 8) * DD + col]) =
                    make_float2(acc[mt][nt][2], acc[mt][nt][3]);
        }
    }
}

// =====================================================================
// SAGE half 2: acc = g_mean @ Wl; epilogue adds g_z + bl, BN + gated
// residual (full-precision hin) + relu -> hout (+ rounded hr_out + bf16)
// =====================================================================
__global__ void __launch_bounds__(256, 2)
gemm_l(const float* __restrict__ Bl, const float* __restrict__ bl,
       const float* __restrict__ gamma, const float* __restrict__ beta,
       const float* __restrict__ alpha,
       const float* __restrict__ hin,
       float* __restrict__ hout, float* __restrict__ hr_out)
{
    GEMM_PROLOGUE();
    const int bn = blockIdx.y * 128;

    GEMM_MAINLOOP(g_mean, Bl);

    const float al  = 1.f / (1.f + __expf(-alpha[0]));
    const float oma = 1.f - al;
    const float BNS = 0.9999950000374994f;   // 1/sqrt(1+1e-5)

    float blv[4][2], gv[4][2], bev[4][2];
#pragma unroll
    for (int nt = 0; nt < 4; nt++) {
        int col = bn + wn + nt * 8 + fc * 2;
        blv[nt][0] = bl[col];    blv[nt][1] = bl[col + 1];
        gv[nt][0]  = gamma[col]; gv[nt][1]  = gamma[col + 1];
        bev[nt][0] = beta[col];  bev[nt][1] = beta[col + 1];
    }

#pragma unroll
    for (int mt = 0; mt < 4; mt++) {
#pragma unroll
        for (int nt = 0; nt < 4; nt++) {
            int row = bm + wm + mt * 16 + fr;
            int col = bn + wn + nt * 8 + fc * 2;
#pragma unroll
            for (int h = 0; h < 2; h++) {
                int rr = row + h * 8;
                if (rr < NN) {
                    float2 zr = *reinterpret_cast<const float2*>(&g_z[(size_t)rr * DD + col]);
                    float2 rv = *reinterpret_cast<const float2*>(&hin[(size_t)rr * DD + col]);
                    float z0 = fmaf((acc[mt][nt][h*2]   + zr.x + blv[nt][0]) * BNS, gv[nt][0], bev[nt][0]);
                    float z1 = fmaf((acc[mt][nt][h*2+1] + zr.y + blv[nt][1]) * BNS, gv[nt][1], bev[nt][1]);
                    float o0 = fmaxf(fmaf(al, z0, oma * rv.x), 0.f);
                    float o1 = fmaxf(fmaf(al, z1, oma * rv.y), 0.f);
                    *reinterpret_cast<float2*>(&hout[(size_t)rr * DD + col]) = make_float2(o0, o1);
                    if (hr_out) {
                        *reinterpret_cast<float2*>(&hr_out[(size_t)rr * DD + col]) =
                            make_float2(rtf32(o0), rtf32(o1));
                        g_hbf[(size_t)rr * 128 + (col >> 1)] = pack_bf16x2(o0, o1);
                    }
                }
            }
        }
    }
}

// -------- CSR build ----------
__global__ void hist_kernel(const int* __restrict__ ei)
{
    int e = blockIdx.x * blockDim.x + threadIdx.x;
    if (e >= EE) return;
    atomicAdd(&g_cnt[ei[EE + e]], 1);
}

// coalesced smem-staged block scan: 1024 threads x 10 elems
__global__ void scan_kernel()
{
    __shared__ int sh[10240];          // 40 KB
    __shared__ int wsum[32];
    const int tid = threadIdx.x;
    const int lane = tid & 31, wid = tid >> 5;
    const int PER = 10;

    for (int i = tid; i < 10240; i += 1024)
        sh[i] = (i < NN) ? g_cnt[i] : 0;
    __syncthreads();

    int base = tid * PER;
    int loc[PER];
    int s = 0;
#pragma unroll
    for (int j = 0; j < PER; j++) {
        s += sh[base + j];
        loc[j] = s;
    }
    int ssum = s;
#pragma unroll
    for (int off = 1; off < 32; off <<= 1) {
        int t = __shfl_up_sync(0xffffffffu, ssum, off);
        if (lane >= off) ssum += t;
    }
    if (lane == 31) wsum[wid] = ssum;
    __syncthreads();
    if (wid == 0) {
        int w = wsum[lane];
#pragma unroll
        for (int off = 1; off < 32; off <<= 1) {
            int t = __shfl_up_sync(0xffffffffu, w, off);
            if (lane >= off) w += t;
        }
        wsum[lane] = w;
    }
    __syncthreads();

    int offset = ssum - s + (wid > 0 ? wsum[wid - 1] : 0);
#pragma unroll
    for (int j = 0; j < PER; j++)
        sh[base + j] = offset + loc[j];
    __syncthreads();

    if (tid == 0) { g_rowptr[0] = 0; g_fill[0] = 0; }
    for (int i = tid; i < NN; i += 1024) {
        int incl = sh[i];
        g_rowptr[i + 1] = incl;
        if (i > 0) g_fill[i] = sh[i - 1];
    }
}

__global__ void scatter_kernel(const int* __restrict__ ei)
{
    int e = blockIdx.x * blockDim.x + threadIdx.x;
    if (e >= EE) return;
    int src = ei[e];
    int dst = ei[EE + e];
    int pos = atomicAdd(&g_fill[dst], 1);
    g_srcs[pos] = src;
}

// -------- TransformerConv: warp per node, single-pass softmax,
// bf16x2 k/v gathers (half bytes) ----------
__global__ void attn_kernel()
{
    int gw = (blockIdx.x * blockDim.x + threadIdx.x) >> 5;
    int lane = threadIdx.x & 31;
    if (gw >= NN) return;
    int beg = g_rowptr[gw], end = g_rowptr[gw + 1];

    float2 qr[4];
#pragma unroll
    for (int r = 0; r < 4; r++)
        qr[r] = *reinterpret_cast<const float2*>(&g_q[(size_t)gw * DD + (r * 32 + lane) * 2]);

    float2 acc[4];
#pragma unroll
    for (int r = 0; r < 4; r++) acc[r] = make_float2(0.f, 0.f);
    float ssum = 0.f;

    for (int e = beg; e < end; e++) {
        int src = g_srcs[e];
        const uint32_t* kp = &g_kbf[(size_t)src * 128];
        const uint32_t* vp = &g_vbf[(size_t)src * 128];
        float p = 0.f;
#pragma unroll
        for (int r = 0; r < 4; r++) {
            uint32_t ku = kp[r * 32 + lane];
            p = fmaf(qr[r].x, __uint_as_float(ku << 16), p);
            p = fmaf(qr[r].y, __uint_as_float(ku & 0xffff0000u), p);
        }
#pragma unroll
        for (int off = 16; off; off >>= 1) p += __shfl_xor_sync(0xffffffffu, p, off);
        float w = __expf(p * 0.0625f);     // / sqrt(256)
        ssum += w;
#pragma unroll
        for (int r = 0; r < 4; r++) {
            uint32_t vu = vp[r * 32 + lane];
            acc[r].x = fmaf(w, __uint_as_float(vu << 16), acc[r].x);
            acc[r].y = fmaf(w, __uint_as_float(vu & 0xffff0000u), acc[r].y);
        }
    }

    float inv = (end > beg) ? (1.f / ssum) : 0.f;
#pragma unroll
    for (int r = 0; r < 4; r++) {
        int p2 = r * 32 + lane;
        float2 sv = *reinterpret_cast<const float2*>(&g_s[(size_t)gw * DD + p2 * 2]);
        float o0 = fmaxf(acc[r].x * inv + sv.x, 0.f);
        float o1 = fmaxf(acc[r].y * inv + sv.y, 0.f);
        *reinterpret_cast<float2*>(&g_hA[(size_t)gw * DD + p2 * 2])  = make_float2(o0, o1);
        *reinterpret_cast<float2*>(&g_hrA[(size_t)gw * DD + p2 * 2]) = make_float2(rtf32(o0), rtf32(o1));
        g_hbf[(size_t)gw * 128 + p2] = pack_bf16x2(o0, o1);
    }
}

// -------- SAGE mean: warp per node, bf16x2 gather (half bytes) ----------
__global__ void mean_kernel()
{
    int gw = (blockIdx.x * blockDim.x + threadIdx.x) >> 5;
    int lane = threadIdx.x & 31;
    if (gw >= NN) return;
    int beg = g_rowptr[gw], end = g_rowptr[gw + 1];

    float2 acc[4];
#pragma unroll
    for (int r = 0; r < 4; r++) acc[r] = make_float2(0.f, 0.f);
    for (int e = beg; e < end; e++) {
        int src = g_srcs[e];
        const uint32_t* hp = &g_hbf[(size_t)src * 128];
#pragma unroll
        for (int r = 0; r < 4; r++) {
            uint32_t u = hp[r * 32 + lane];
            acc[r].x += __uint_as_float(u << 16);          // lo bf16 -> fp32
            acc[r].y += __uint_as_float(u & 0xffff0000u);  // hi bf16 -> fp32
        }
    }
    int deg = end - beg;
    float invd = 1.f / (float)(deg > 0 ? deg : 1);
#pragma unroll
    for (int r = 0; r < 4; r++) {
        int p2 = r * 32 + lane;
        *reinterpret_cast<float2*>(&g_mean[(size_t)gw * DD + p2 * 2]) =
            make_float2(rtf32(acc[r].x * invd), rtf32(acc[r].y * invd));
    }
}

// -------- cached fork-join resources (host objects only; no device mem) ----
static cudaStream_t g_s2 = nullptr;
static cudaEvent_t  g_evF = nullptr, g_evJ = nullptr;
static cudaEvent_t  g_evA[3] = {nullptr, nullptr, nullptr};
static cudaEvent_t  g_evB[3] = {nullptr, nullptr, nullptr};

// -------- launch ----------
extern "C" void kernel_launch(void* const* d_in, const int* in_sizes, int n_in,
                              void* d_out, int out_size)
{
    const float* x     = (const float*)d_in[0];
    const int*   ei    = (const int*)d_in[1];       // int32 (jax x64 disabled)
    const float* Wq    = (const float*)d_in[2];
    const float* bq    = (const float*)d_in[3];
    const float* Wk    = (const float*)d_in[4];
    const float* bk    = (const float*)d_in[5];
    const float* Wv    = (const float*)d_in[6];
    const float* bv    = (const float*)d_in[7];
    const float* Ws    = (const float*)d_in[8];
    const float* bs    = (const float*)d_in[9];
    const float* Wl    = (const float*)d_in[10];
    const float* bl    = (const float*)d_in[11];
    const float* Wr    = (const float*)d_in[12];
    const float* gamma = (const float*)d_in[13];
    const float* beta  = (const float*)d_in[14];
    const float* alpha = (const float*)d_in[15];
    float*       out   = (float*)d_out;

    float *hA, *hB, *hrA, *hrB, *wr;
    void* cntp;
    cudaGetSymbolAddress((void**)&hA,  g_hA);
    cudaGetSymbolAddress((void**)&hB,  g_hB);
    cudaGetSymbolAddress((void**)&hrA, g_hrA);
    cudaGetSymbolAddress((void**)&hrB, g_hrB);
    cudaGetSymbolAddress((void**)&wr,  g_wr);
    cudaGetSymbolAddress(&cntp,        g_cnt);

    if (g_s2 == nullptr) {
        cudaStreamCreateWithFlags(&g_s2, cudaStreamNonBlocking);
        cudaEventCreateWithFlags(&g_evF, cudaEventDisableTiming);
        cudaEventCreateWithFlags(&g_evJ, cudaEventDisableTiming);
        for (int i = 0; i < 3; i++) {
            cudaEventCreateWithFlags(&g_evA[i], cudaEventDisableTiming);
            cudaEventCreateWithFlags(&g_evB[i], cudaEventDisableTiming);
        }
    }

    cudaFuncSetAttribute(gemm_qkvs, cudaFuncAttributeMaxDynamicSharedMemorySize, SMEM_BYTES);
    cudaFuncSetAttribute(gemm_r,    cudaFuncAttributeMaxDynamicSharedMemorySize, SMEM_BYTES);
    cudaFuncSetAttribute(gemm_l,    cudaFuncAttributeMaxDynamicSharedMemorySize, SMEM_BYTES);

    const int MT = (NN + 127) / 128;   // 79
    const int PREPV = NDTOT / 4 + 10 * (WSZ / 4);

    // ---- fork: CSR chain on g_s2, concurrent with prep + QKVS ----
    cudaEventRecord(g_evF, 0);
    cudaStreamWaitEvent(g_s2, g_evF, 0);

    cudaMemsetAsync(cntp, 0, NN * sizeof(int), g_s2);
    hist_kernel<<<(EE + 255) / 256, 256, 0, g_s2>>>(ei);
    scan_kernel<<<1, 1024, 0, g_s2>>>();
    scatter_kernel<<<(EE + 255) / 256, 256, 0, g_s2>>>(ei);

    // main stream: prep (float4) + fused projections
    round_prep<<<(PREPV + 255) / 256, 256>>>((const float4*)x,
                                             (const float4*)Wq, (const float4*)Wk,
                                             (const float4*)Wv, (const float4*)Ws,
                                             (const float4*)Wl, (const float4*)Wr);
    gemm_qkvs<<<dim3(MT, 8), 256, SMEM_BYTES>>>(bq, bk, bv, bs);

    // ---- join ----
    cudaEventRecord(g_evJ, g_s2);
    cudaStreamWaitEvent(0, g_evJ, 0);

    // TransformerConv (single pass, bf16 gathers)
    attn_kernel<<<(NN * 32 + 255) / 256, 256>>>();

    // 3 SAGE layers: mean (stream2, bf16 gather) overlaps gemm_r, then gemm_l
    float* hin  = hA;
    float* hrin = hrA;
    for (int l = 0; l < 3; l++) {
        cudaEventRecord(g_evA[l], 0);
        cudaStreamWaitEvent(g_s2, g_evA[l], 0);
        mean_kernel<<<(NN * 32 + 255) / 256, 256, 0, g_s2>>>();
        cudaEventRecord(g_evB[l], g_s2);

        gemm_r<<<dim3(MT, 2), 256, SMEM_BYTES>>>(wr + (size_t)(7 + l) * WSZ, hrin);

        cudaStreamWaitEvent(0, g_evB[l], 0);

        float* hout  = (l == 2) ? out : ((l == 0) ? hB : hA);
        float* hrout = (l == 2) ? nullptr : ((hrin == hrA) ? hrB : hrA);
        gemm_l<<<dim3(MT, 2), 256, SMEM_BYTES>>>(wr + (size_t)(4 + l) * WSZ,
                                                 bl + (size_t)l * 256,
                                                 gamma + (size_t)l * 256, beta + (size_t)l * 256,
                                                 alpha, hin, hout, hrout);
        hin  = hout;
        hrin = hrout;
    }
}

// round 17
// speedup vs baseline: 1.2181x; 1.0631x over previous
#include <cuda_runtime.h>
#include <cstdint>

#define NN 10000
#define EE 320000
#define DD 256
#define NDTOT (NN*DD)
#define WSZ 65536

// -------- scratch (static device globals; no allocation) ----------
__device__ float g_q[NDTOT];
__device__ float g_s[NDTOT];
__device__ float g_hA[NDTOT];
__device__ float g_hB[NDTOT];
__device__ float g_hrA[NDTOT];        // tf32-rounded h, ping
__device__ float g_hrB[NDTOT];        // tf32-rounded h, pong
__device__ uint32_t g_hbf[NDTOT/2];   // bf16x2-packed h (mean-gather input)
__device__ uint32_t g_kbf[NDTOT/2];   // bf16x2-packed k (attn gather input)
__device__ uint32_t g_vbf[NDTOT/2];   // bf16x2-packed v (attn gather input)
__device__ float g_xr[NDTOT];         // tf32-rounded x
__device__ float g_wr[10*WSZ];        // rounded weights: Wq,Wk,Wv,Ws,Wl0..2,Wr0..2
__device__ float g_mean[NDTOT];       // tf32-rounded at production
__device__ float g_z[NDTOT];          // partial h@Wr accumulator
__device__ int   g_rowptr[NN + 1];
__device__ int   g_srcs[EE];
__device__ int   g_cnt[NN];
__device__ int   g_fill[NN];

// -------- helpers ----------
__device__ __forceinline__ float rtf32(float f)
{
    uint32_t u;
    asm("cvt.rna.tf32.f32 %0, %1;" : "=r"(u) : "f"(f));
    return __uint_as_float(u);
}

__device__ __forceinline__ uint32_t pack_bf16x2(float lo, float hi)
{
    uint32_t u;
    asm("cvt.rn.bf16x2.f32 %0, %1, %2;" : "=r"(u) : "f"(hi), "f"(lo));
    return u;
}

__device__ __forceinline__ void mma_tf32(float* c, const uint32_t* a, const uint32_t* b)
{
    asm volatile(
        "mma.sync.aligned.m16n8k8.row.col.f32.tf32.tf32.f32 "
        "{%0,%1,%2,%3}, {%4,%5,%6,%7}, {%8,%9}, {%0,%1,%2,%3};"
        : "+f"(c[0]), "+f"(c[1]), "+f"(c[2]), "+f"(c[3])
        : "r"(a[0]), "r"(a[1]), "r"(a[2]), "r"(a[3]), "r"(b[0]), "r"(b[1]));
}

__device__ __forceinline__ void cpasync16(uint32_t dst, const void* src, int szbytes)
{
    asm volatile("cp.async.ca.shared.global [%0], [%1], 16, %2;"
                 :: "r"(dst), "l"(src), "r"(szbytes));
}
__device__ __forceinline__ void cpasync_commit() { asm volatile("cp.async.commit_group;"); }
__device__ __forceinline__ void cpasync_wait1()  { asm volatile("cp.async.wait_group 1;"); }
__device__ __forceinline__ void cpasync_wait0()  { asm volatile("cp.async.wait_group 0;"); }

// -------- prep: tf32-round x and all weights into scratch (float4) --------
__global__ void round_prep(const float4* __restrict__ x,
                           const float4* __restrict__ Wq, const float4* __restrict__ Wk,
                           const float4* __restrict__ Wv, const float4* __restrict__ Ws,
                           const float4* __restrict__ Wl, const float4* __restrict__ Wr)
{
    int i = blockIdx.x * blockDim.x + threadIdx.x;
    const int XV = NDTOT / 4;           // 640000
    const int WV = WSZ / 4;             // 16384
    const int totalv = XV + 10 * WV;
    if (i >= totalv) return;
    float4 v;
    float4* dst;
    if (i < XV) {
        v = x[i];
        dst = reinterpret_cast<float4*>(g_xr) + i;
    } else {
        int j = i - XV;
        int m = j >> 14, o = j & (WV - 1);
        const float4* src;
        if      (m == 0) src = Wq;
        else if (m == 1) src = Wk;
        else if (m == 2) src = Wv;
        else if (m == 3) src = Ws;
        else if (m <  7) src = Wl + (size_t)(m - 4) * WV;
        else             src = Wr + (size_t)(m - 7) * WV;
        v = src[o];
        dst = reinterpret_cast<float4*>(g_wr) + j;
    }
    v.x = rtf32(v.x); v.y = rtf32(v.y); v.z = rtf32(v.z); v.w = rtf32(v.w);
    *dst = v;
}

#define APAD 36
#define BPAD 136
#define ASZ (128*APAD)
#define BSZ (32*BPAD)
#define SMEM_BYTES ((2*ASZ + 2*BSZ) * 4)   // 71680

// ---- issue one chunk (A 128x32 from Asrc at col kt, B 32x128 from Bsrc) ----
#define ISSUE_CHUNK(Asrc, Bsrc, kt, buf)                                        \
    {                                                                           \
        uint32_t abase = sbase + (uint32_t)((buf) * ASZ) * 4u;                  \
        uint32_t bbase = sbase + (uint32_t)(2 * ASZ + (buf) * BSZ) * 4u;        \
        _Pragma("unroll")                                                       \
        for (int i = 0; i < 4; i++) {                                           \
            int idx = i * 256 + tid;                                            \
            int ar = idx >> 3, acq = (idx & 7) * 4;                             \
            int grow = bm + ar;                                                 \
            int sz = (grow < NN) ? 16 : 0;                                      \
            cpasync16(abase + (uint32_t)(ar * APAD + acq) * 4u,                 \
                      (Asrc) + (size_t)grow * DD + (kt) + acq, sz);             \
        }                                                                       \
        _Pragma("unroll")                                                       \
        for (int i = 0; i < 4; i++) {                                           \
            int idx = i * 256 + tid;                                            \
            int br = idx >> 5, bcq = (idx & 31) * 4;                            \
            cpasync16(bbase + (uint32_t)(br * BPAD + bcq) * 4u,                 \
                      (Bsrc) + (size_t)((kt) + br) * DD + bn + bcq, 16);        \
        }                                                                       \
        cpasync_commit();                                                       \
    }

#define COMPUTE_CHUNK(buf)                                                      \
    {                                                                           \
        const float* pA = s_dyn + (buf) * ASZ;                                  \
        const float* pB = s_dyn + 2 * ASZ + (buf) * BSZ;                        \
        _Pragma("unroll")                                                       \
        for (int k8 = 0; k8 < 4; k8++) {                                        \
            const int kb = k8 * 8;                                              \
            uint32_t af[4][4], bf[4][2];                                        \
            _Pragma("unroll")                                                   \
            for (int mt = 0; mt < 4; mt++) {                                    \
                int mr = wm + mt * 16 + fr;                                     \
                af[mt][0] = __float_as_uint(pA[mr * APAD + kb + fc]);           \
                af[mt][1] = __float_as_uint(pA[(mr + 8) * APAD + kb + fc]);     \
                af[mt][2] = __float_as_uint(pA[mr * APAD + kb + fc + 4]);       \
                af[mt][3] = __float_as_uint(pA[(mr + 8) * APAD + kb + fc + 4]); \
            }                                                                   \
            _Pragma("unroll")                                                   \
            for (int nt = 0; nt < 4; nt++) {                                    \
                int nc = wn + nt * 8 + fr;                                      \
                bf[nt][0] = __float_as_uint(pB[(kb + fc) * BPAD + nc]);         \
                bf[nt][1] = __float_as_uint(pB[(kb + fc + 4) * BPAD + nc]);     \
            }                                                                   \
            _Pragma("unroll")                                                   \
            for (int mt = 0; mt < 4; mt++)                                      \
                _Pragma("unroll")                                               \
                for (int nt = 0; nt < 4; nt++)                                  \
                    mma_tf32(acc[mt][nt], af[mt], bf[nt]);                      \
        }                                                                       \
    }

#define GEMM_PROLOGUE()                                                         \
    extern __shared__ float s_dyn[];                                            \
    const uint32_t sbase = (uint32_t)__cvta_generic_to_shared(s_dyn);           \
    const int tid  = threadIdx.x;                                               \
    const int lane = tid & 31;                                                  \
    const int warp = tid >> 5;                                                  \
    const int wm = (warp >> 2) * 64;                                            \
    const int wn = (warp & 3) * 32;                                             \
    const int fr = lane >> 2;                                                   \
    const int fc = lane & 3;                                                    \
    const int bm = blockIdx.x * 128;                                            \
    float acc[4][4][4];                                                         \
    _Pragma("unroll")                                                           \
    for (int mt = 0; mt < 4; mt++)                                              \
        _Pragma("unroll")                                                       \
        for (int nt = 0; nt < 4; nt++)                                          \
            _Pragma("unroll")                                                   \
            for (int r = 0; r < 4; r++) acc[mt][nt][r] = 0.f;

#define GEMM_MAINLOOP(Asrc, Bsrc)                                               \
    {                                                                           \
        const int NC = 8;                                                       \
        ISSUE_CHUNK(Asrc, Bsrc, 0, 0);                                          \
        ISSUE_CHUNK(Asrc, Bsrc, 32, 1);                                         \
        for (int c = 0; c < NC; c++) {                                          \
            if (c + 1 < NC) cpasync_wait1(); else cpasync_wait0();              \
            __syncthreads();                                                    \
            COMPUTE_CHUNK(c & 1);                                               \
            __syncthreads();                                                    \
            if (c + 2 < NC) ISSUE_CHUNK(Asrc, Bsrc, (c + 2) * 32, c & 1);       \
        }                                                                       \
    }

// =====================================================================
// Fused QKVS projection: A = g_xr (pre-rounded), B = g_wr[mat]
// grid (79, 8). q,s stored fp32; k,v stored ONLY as packed bf16x2.
// =====================================================================
__global__ void __launch_bounds__(256, 2)
gemm_qkvs(const float* __restrict__ bq, const float* __restrict__ bk,
          const float* __restrict__ bv, const float* __restrict__ bs)
{
    GEMM_PROLOGUE();
    const int mat = blockIdx.y >> 1;
    const int bn  = (blockIdx.y & 1) * 128;

    const float* B = g_wr + (size_t)mat * WSZ;
    const float* bias;
    float* C = nullptr;
    uint32_t* BF = nullptr;
    if      (mat == 0) { bias = bq; C = g_q; }
    else if (mat == 1) { bias = bk; BF = g_kbf; }
    else if (mat == 2) { bias = bv; BF = g_vbf; }
    else               { bias = bs; C = g_s; }

    GEMM_MAINLOOP(g_xr, B);

    float bb[4][2];
#pragma unroll
    for (int nt = 0; nt < 4; nt++) {
        int col = bn + wn + nt * 8 + fc * 2;
        bb[nt][0] = bias[col]; bb[nt][1] = bias[col + 1];
    }
#pragma unroll
    for (int mt = 0; mt < 4; mt++) {
#pragma unroll
        for (int nt = 0; nt < 4; nt++) {
            int row = bm + wm + mt * 16 + fr;
            int col = bn + wn + nt * 8 + fc * 2;
#pragma unroll
            for (int h = 0; h < 2; h++) {
                int rr = row + h * 8;
                if (rr < NN) {
                    float o0 = acc[mt][nt][h*2]   + bb[nt][0];
                    float o1 = acc[mt][nt][h*2+1] + bb[nt][1];
                    if (C)
                        *reinterpret_cast<float2*>(&C[(size_t)rr * DD + col]) = make_float2(o0, o1);
                    else
                        BF[(size_t)rr * 128 + (col >> 1)] = pack_bf16x2(o0, o1);
                }
            }
        }
    }
}

// =====================================================================
// SAGE half 1: g_z = hr_in @ Wr   (no epilogue; runs concurrent w/ mean)
// =====================================================================
__global__ void __launch_bounds__(256, 2)
gemm_r(const float* __restrict__ Br, const float* __restrict__ hr_in)
{
    GEMM_PROLOGUE();
    const int bn = blockIdx.y * 128;

    GEMM_MAINLOOP(hr_in, Br);

#pragma unroll
    for (int mt = 0; mt < 4; mt++) {
#pragma unroll
        for (int nt = 0; nt < 4; nt++) {
            int row = bm + wm + mt * 16 + fr;
            int col = bn + wn + nt * 8 + fc * 2;
            if (row < NN)
                *reinterpret_cast<float2*>(&g_z[(size_t)row * DD + col]) =
                    make_float2(acc[mt][nt][0], acc[mt][nt][1]);
            if (row + 8 < NN)
                *reinterpret_cast<float2*>(&g_z[(size_t)(row + 8) * DD + col]) =
                    make_float2(acc[mt][nt][2], acc[mt][nt][3]);
        }
    }
}

// =====================================================================
// SAGE half 2: acc = g_mean @ Wl; epilogue adds g_z + bl, BN + gated
// residual (full-precision hin) + relu -> hout (+ rounded hr_out + bf16)
// =====================================================================
__global__ void __launch_bounds__(256, 2)
gemm_l(const float* __restrict__ Bl, const float* __restrict__ bl,
       const float* __restrict__ gamma, const float* __restrict__ beta,
       const float* __restrict__ alpha,
       const float* __restrict__ hin,
       float* __restrict__ hout, float* __restrict__ hr_out)
{
    GEMM_PROLOGUE();
    const int bn = blockIdx.y * 128;

    GEMM_MAINLOOP(g_mean, Bl);

    const float al  = 1.f / (1.f + __expf(-alpha[0]));
    const float oma = 1.f - al;
    const float BNS = 0.9999950000374994f;   // 1/sqrt(1+1e-5)

    float blv[4][2], gv[4][2], bev[4][2];
#pragma unroll
    for (int nt = 0; nt < 4; nt++) {
        int col = bn + wn + nt * 8 + fc * 2;
        blv[nt][0] = bl[col];    blv[nt][1] = bl[col + 1];
        gv[nt][0]  = gamma[col]; gv[nt][1]  = gamma[col + 1];
        bev[nt][0] = beta[col];  bev[nt][1] = beta[col + 1];
    }

#pragma unroll
    for (int mt = 0; mt < 4; mt++) {
#pragma unroll
        for (int nt = 0; nt < 4; nt++) {
            int row = bm + wm + mt * 16 + fr;
            int col = bn + wn + nt * 8 + fc * 2;
#pragma unroll
            for (int h = 0; h < 2; h++) {
                int rr = row + h * 8;
                if (rr < NN) {
                    float2 zr = *reinterpret_cast<const float2*>(&g_z[(size_t)rr * DD + col]);
                    float2 rv = *reinterpret_cast<const float2*>(&hin[(size_t)rr * DD + col]);
                    float z0 = fmaf((acc[mt][nt][h*2]   + zr.x + blv[nt][0]) * BNS, gv[nt][0], bev[nt][0]);
                    float z1 = fmaf((acc[mt][nt][h*2+1] + zr.y + blv[nt][1]) * BNS, gv[nt][1], bev[nt][1]);
                    float o0 = fmaxf(fmaf(al, z0, oma * rv.x), 0.f);
                    float o1 = fmaxf(fmaf(al, z1, oma * rv.y), 0.f);
                    *reinterpret_cast<float2*>(&hout[(size_t)rr * DD + col]) = make_float2(o0, o1);
                    if (hr_out) {
                        *reinterpret_cast<float2*>(&hr_out[(size_t)rr * DD + col]) =
                            make_float2(rtf32(o0), rtf32(o1));
                        g_hbf[(size_t)rr * 128 + (col >> 1)] = pack_bf16x2(o0, o1);
                    }
                }
            }
        }
    }
}

// -------- CSR build ----------
__global__ void hist_kernel(const int* __restrict__ ei)
{
    int e = blockIdx.x * blockDim.x + threadIdx.x;
    if (e >= EE) return;
    atomicAdd(&g_cnt[ei[EE + e]], 1);
}

// coalesced smem-staged block scan: 1024 threads x 10 elems
__global__ void scan_kernel()
{
    __shared__ int sh[10240];          // 40 KB
    __shared__ int wsum[32];
    const int tid = threadIdx.x;
    const int lane = tid & 31, wid = tid >> 5;
    const int PER = 10;

    for (int i = tid; i < 10240; i += 1024)
        sh[i] = (i < NN) ? g_cnt[i] : 0;
    __syncthreads();

    int base = tid * PER;
    int loc[PER];
    int s = 0;
#pragma unroll
    for (int j = 0; j < PER; j++) {
        s += sh[base + j];
        loc[j] = s;
    }
    int ssum = s;
#pragma unroll
    for (int off = 1; off < 32; off <<= 1) {
        int t = __shfl_up_sync(0xffffffffu, ssum, off);
        if (lane >= off) ssum += t;
    }
    if (lane == 31) wsum[wid] = ssum;
    __syncthreads();
    if (wid == 0) {
        int w = wsum[lane];
#pragma unroll
        for (int off = 1; off < 32; off <<= 1) {
            int t = __shfl_up_sync(0xffffffffu, w, off);
            if (lane >= off) w += t;
        }
        wsum[lane] = w;
    }
    __syncthreads();

    int offset = ssum - s + (wid > 0 ? wsum[wid - 1] : 0);
#pragma unroll
    for (int j = 0; j < PER; j++)
        sh[base + j] = offset + loc[j];
    __syncthreads();

    if (tid == 0) { g_rowptr[0] = 0; g_fill[0] = 0; }
    for (int i = tid; i < NN; i += 1024) {
        int incl = sh[i];
        g_rowptr[i + 1] = incl;
        if (i > 0) g_fill[i] = sh[i - 1];
    }
}

__global__ void scatter_kernel(const int* __restrict__ ei)
{
    int e = blockIdx.x * blockDim.x + threadIdx.x;
    if (e >= EE) return;
    int src = ei[e];
    int dst = ei[EE + e];
    int pos = atomicAdd(&g_fill[dst], 1);
    g_srcs[pos] = src;
}

// -------- TransformerConv: warp per node, single-pass softmax,
// bf16x2 k/v gathers, 2-way edge unrolling (pipelined shuffle chains) ----
__global__ void attn_kernel()
{
    int gw = (blockIdx.x * blockDim.x + threadIdx.x) >> 5;
    int lane = threadIdx.x & 31;
    if (gw >= NN) return;
    int beg = g_rowptr[gw], end = g_rowptr[gw + 1];

    float2 qr[4];
#pragma unroll
    for (int r = 0; r < 4; r++)
        qr[r] = *reinterpret_cast<const float2*>(&g_q[(size_t)gw * DD + (r * 32 + lane) * 2]);

    float2 acc[4];
#pragma unroll
    for (int r = 0; r < 4; r++) acc[r] = make_float2(0.f, 0.f);
    float ssum = 0.f;

    int e = beg;
    for (; e + 1 < end; e += 2) {
        int s0 = g_srcs[e], s1 = g_srcs[e + 1];
        const uint32_t* k0 = &g_kbf[(size_t)s0 * 128];
        const uint32_t* k1 = &g_kbf[(size_t)s1 * 128];
        const uint32_t* v0 = &g_vbf[(size_t)s0 * 128];
        const uint32_t* v1 = &g_vbf[(size_t)s1 * 128];
        float p0 = 0.f, p1 = 0.f;
#pragma unroll
        for (int r = 0; r < 4; r++) {
            uint32_t ku0 = k0[r * 32 + lane];
            uint32_t ku1 = k1[r * 32 + lane];
            p0 = fmaf(qr[r].x, __uint_as_float(ku0 << 16), p0);
            p0 = fmaf(qr[r].y, __uint_as_float(ku0 & 0xffff0000u), p0);
            p1 = fmaf(qr[r].x, __uint_as_float(ku1 << 16), p1);
            p1 = fmaf(qr[r].y, __uint_as_float(ku1 & 0xffff0000u), p1);
        }
#pragma unroll
        for (int off = 16; off; off >>= 1) {
            p0 += __shfl_xor_sync(0xffffffffu, p0, off);
            p1 += __shfl_xor_sync(0xffffffffu, p1, off);
        }
        float w0 = __expf(p0 * 0.0625f);
        float w1 = __expf(p1 * 0.0625f);
        ssum += w0;
        ssum += w1;
#pragma unroll
        for (int r = 0; r < 4; r++) {
            uint32_t vu0 = v0[r * 32 + lane];
            uint32_t vu1 = v1[r * 32 + lane];
            acc[r].x = fmaf(w0, __uint_as_float(vu0 << 16), acc[r].x);
            acc[r].y = fmaf(w0, __uint_as_float(vu0 & 0xffff0000u), acc[r].y);
            acc[r].x = fmaf(w1, __uint_as_float(vu1 << 16), acc[r].x);
            acc[r].y = fmaf(w1, __uint_as_float(vu1 & 0xffff0000u), acc[r].y);
        }
    }
    if (e < end) {
        int s0 = g_srcs[e];
        const uint32_t* k0 = &g_kbf[(size_t)s0 * 128];
        const uint32_t* v0 = &g_vbf[(size_t)s0 * 128];
        float p0 = 0.f;
#pragma unroll
        for (int r = 0; r < 4; r++) {
            uint32_t ku0 = k0[r * 32 + lane];
            p0 = fmaf(qr[r].x, __uint_as_float(ku0 << 16), p0);
            p0 = fmaf(qr[r].y, __uint_as_float(ku0 & 0xffff0000u), p0);
        }
#pragma unroll
        for (int off = 16; off; off >>= 1) p0 += __shfl_xor_sync(0xffffffffu, p0, off);
        float w0 = __expf(p0 * 0.0625f);
        ssum += w0;
#pragma unroll
        for (int r = 0; r < 4; r++) {
            uint32_t vu0 = v0[r * 32 + lane];
            acc[r].x = fmaf(w0, __uint_as_float(vu0 << 16), acc[r].x);
            acc[r].y = fmaf(w0, __uint_as_float(vu0 & 0xffff0000u), acc[r].y);
        }
    }

    float inv = (end > beg) ? (1.f / ssum) : 0.f;
#pragma unroll
    for (int r = 0; r < 4; r++) {
        int p2 = r * 32 + lane;
        float2 sv = *reinterpret_cast<const float2*>(&g_s[(size_t)gw * DD + p2 * 2]);
        float o0 = fmaxf(acc[r].x * inv + sv.x, 0.f);
        float o1 = fmaxf(acc[r].y * inv + sv.y, 0.f);
        *reinterpret_cast<float2*>(&g_hA[(size_t)gw * DD + p2 * 2])  = make_float2(o0, o1);
        *reinterpret_cast<float2*>(&g_hrA[(size_t)gw * DD + p2 * 2]) = make_float2(rtf32(o0), rtf32(o1));
        g_hbf[(size_t)gw * 128 + p2] = pack_bf16x2(o0, o1);
    }
}

// -------- SAGE mean: warp per node, bf16x2 gather, 2-way unroll ----------
__global__ void mean_kernel()
{
    int gw = (blockIdx.x * blockDim.x + threadIdx.x) >> 5;
    int lane = threadIdx.x & 31;
    if (gw >= NN) return;
    int beg = g_rowptr[gw], end = g_rowptr[gw + 1];

    float2 acc[4];
#pragma unroll
    for (int r = 0; r < 4; r++) acc[r] = make_float2(0.f, 0.f);
    int e = beg;
    for (; e + 1 < end; e += 2) {
        const uint32_t* h0 = &g_hbf[(size_t)g_srcs[e] * 128];
        const uint32_t* h1 = &g_hbf[(size_t)g_srcs[e + 1] * 128];
#pragma unroll
        for (int r = 0; r < 4; r++) {
            uint32_t u0 = h0[r * 32 + lane];
            uint32_t u1 = h1[r * 32 + lane];
            acc[r].x += __uint_as_float(u0 << 16);
            acc[r].y += __uint_as_float(u0 & 0xffff0000u);
            acc[r].x += __uint_as_float(u1 << 16);
            acc[r].y += __uint_as_float(u1 & 0xffff0000u);
        }
    }
    if (e < end) {
        const uint32_t* h0 = &g_hbf[(size_t)g_srcs[e] * 128];
#pragma unroll
        for (int r = 0; r < 4; r++) {
            uint32_t u0 = h0[r * 32 + lane];
            acc[r].x += __uint_as_float(u0 << 16);
            acc[r].y += __uint_as_float(u0 & 0xffff0000u);
        }
    }
    int deg = end - beg;
    float invd = 1.f / (float)(deg > 0 ? deg : 1);
#pragma unroll
    for (int r = 0; r < 4; r++) {
        int p2 = r * 32 + lane;
        *reinterpret_cast<float2*>(&g_mean[(size_t)gw * DD + p2 * 2]) =
            make_float2(rtf32(acc[r].x * invd), rtf32(acc[r].y * invd));
    }
}

// -------- cached fork-join resources (host objects only; no device mem) ----
static cudaStream_t g_s2 = nullptr;
static cudaEvent_t  g_evF = nullptr, g_evJ = nullptr;
static cudaEvent_t  g_evA[3] = {nullptr, nullptr, nullptr};
static cudaEvent_t  g_evB[3] = {nullptr, nullptr, nullptr};

// -------- launch ----------
extern "C" void kernel_launch(void* const* d_in, const int* in_sizes, int n_in,
                              void* d_out, int out_size)
{
    const float* x     = (const float*)d_in[0];
    const int*   ei    = (const int*)d_in[1];       // int32 (jax x64 disabled)
    const float* Wq    = (const float*)d_in[2];
    const float* bq    = (const float*)d_in[3];
    const float* Wk    = (const float*)d_in[4];
    const float* bk    = (const float*)d_in[5];
    const float* Wv    = (const float*)d_in[6];
    const float* bv    = (const float*)d_in[7];
    const float* Ws    = (const float*)d_in[8];
    const float* bs    = (const float*)d_in[9];
    const float* Wl    = (const float*)d_in[10];
    const float* bl    = (const float*)d_in[11];
    const float* Wr    = (const float*)d_in[12];
    const float* gamma = (const float*)d_in[13];
    const float* beta  = (const float*)d_in[14];
    const float* alpha = (const float*)d_in[15];
    float*       out   = (float*)d_out;

    float *hA, *hB, *hrA, *hrB, *wr;
    void* cntp;
    cudaGetSymbolAddress((void**)&hA,  g_hA);
    cudaGetSymbolAddress((void**)&hB,  g_hB);
    cudaGetSymbolAddress((void**)&hrA, g_hrA);
    cudaGetSymbolAddress((void**)&hrB, g_hrB);
    cudaGetSymbolAddress((void**)&wr,  g_wr);
    cudaGetSymbolAddress(&cntp,        g_cnt);

    if (g_s2 == nullptr) {
        cudaStreamCreateWithFlags(&g_s2, cudaStreamNonBlocking);
        cudaEventCreateWithFlags(&g_evF, cudaEventDisableTiming);
        cudaEventCreateWithFlags(&g_evJ, cudaEventDisableTiming);
        for (int i = 0; i < 3; i++) {
            cudaEventCreateWithFlags(&g_evA[i], cudaEventDisableTiming);
            cudaEventCreateWithFlags(&g_evB[i], cudaEventDisableTiming);
        }
    }

    cudaFuncSetAttribute(gemm_qkvs, cudaFuncAttributeMaxDynamicSharedMemorySize, SMEM_BYTES);
    cudaFuncSetAttribute(gemm_r,    cudaFuncAttributeMaxDynamicSharedMemorySize, SMEM_BYTES);
    cudaFuncSetAttribute(gemm_l,    cudaFuncAttributeMaxDynamicSharedMemorySize, SMEM_BYTES);

    const int MT = (NN + 127) / 128;   // 79
    const int PREPV = NDTOT / 4 + 10 * (WSZ / 4);

    // ---- fork: CSR chain on g_s2, concurrent with prep + QKVS ----
    cudaEventRecord(g_evF, 0);
    cudaStreamWaitEvent(g_s2, g_evF, 0);

    cudaMemsetAsync(cntp, 0, NN * sizeof(int), g_s2);
    hist_kernel<<<(EE + 255) / 256, 256, 0, g_s2>>>(ei);
    scan_kernel<<<1, 1024, 0, g_s2>>>();
    scatter_kernel<<<(EE + 255) / 256, 256, 0, g_s2>>>(ei);

    // main stream: prep (float4) + fused projections
    round_prep<<<(PREPV + 255) / 256, 256>>>((const float4*)x,
                                             (const float4*)Wq, (const float4*)Wk,
                                             (const float4*)Wv, (const float4*)Ws,
                                             (const float4*)Wl, (const float4*)Wr);
    gemm_qkvs<<<dim3(MT, 8), 256, SMEM_BYTES>>>(bq, bk, bv, bs);

    // ---- join ----
    cudaEventRecord(g_evJ, g_s2);
    cudaStreamWaitEvent(0, g_evJ, 0);

    // TransformerConv (single pass, bf16 gathers, 2-way unroll)
    attn_kernel<<<(NN * 32 + 255) / 256, 256>>>();

    // 3 SAGE layers: mean (stream2, bf16 gather) overlaps gemm_r, then gemm_l
    float* hin  = hA;
    float* hrin = hrA;
    for (int l = 0; l < 3; l++) {
        cudaEventRecord(g_evA[l], 0);
        cudaStreamWaitEvent(g_s2, g_evA[l], 0);
        mean_kernel<<<(NN * 32 + 255) / 256, 256, 0, g_s2>>>();
        cudaEventRecord(g_evB[l], g_s2);

        gemm_r<<<dim3(MT, 2), 256, SMEM_BYTES>>>(wr + (size_t)(7 + l) * WSZ, hrin);

        cudaStreamWaitEvent(0, g_evB[l], 0);

        float* hout  = (l == 2) ? out : ((l == 0) ? hB : hA);
        float* hrout = (l == 2) ? nullptr : ((hrin == hrA) ? hrB : hrA);
        gemm_l<<<dim3(MT, 2), 256, SMEM_BYTES>>>(wr + (size_t)(4 + l) * WSZ,
                                                 bl + (size_t)l * 256,
                                                 gamma + (size_t)l * 256, beta + (size_t)l * 256,
                                                 alpha, hin, hout, hrout);
        hin  = hout;
        hrin = hrout;
    }
}